// round 10
// baseline (speedup 1.0000x reference)
#include <cuda_runtime.h>
#include <cuda_bf16.h>
#include <math.h>
#include <stdint.h>

// ---------------------------------------------------------------------------
// CrossAttention with LoRA — round 9
// gemm warp tile 64x32 (halves LDSM bytes per MMA; smem-BW bound fix)
// B=8, T=1024, S=256, C=1024, H=16, D=64, R=16, SCALING=1/16
// ---------------------------------------------------------------------------

#define Bsz   8
#define Tlen  1024
#define Slen  256
#define Cdim  1024

__device__ __align__(16) __nv_bfloat16 g_xhi[Bsz*Tlen*Cdim], g_xlo[Bsz*Tlen*Cdim];
__device__ __align__(16) __nv_bfloat16 g_fhi[Bsz*Slen*Cdim], g_flo[Bsz*Slen*Cdim];
__device__ __align__(16) __nv_bfloat16 g_yhi[Bsz*Tlen*Cdim], g_ylo[Bsz*Tlen*Cdim];
__device__ __align__(16) __nv_bfloat16 g_wqhi[Cdim*Cdim],   g_wqlo[Cdim*Cdim];
__device__ __align__(16) __nv_bfloat16 g_wfhi[2*Cdim*Cdim], g_wflo[2*Cdim*Cdim];
__device__ __align__(16) __nv_bfloat16 g_wphi[Cdim*Cdim],   g_wplo[Cdim*Cdim];

__device__ __align__(16) __nv_bfloat16 g_qh[Bsz*Tlen*Cdim],     g_ql[Bsz*Tlen*Cdim];
__device__ __align__(16) __nv_bfloat16 g_kvh[Bsz*Slen*2*Cdim],  g_kvl[Bsz*Slen*2*Cdim];

__device__ __align__(16) __nv_bfloat16 g_tqh[Bsz*Tlen*32], g_tql[Bsz*Tlen*32];
__device__ __align__(16) __nv_bfloat16 g_tfh[Bsz*Slen*32], g_tfl[Bsz*Slen*32];
__device__ __align__(16) __nv_bfloat16 g_tph[Bsz*Tlen*32], g_tpl[Bsz*Tlen*32];
__device__ __align__(16) __nv_bfloat16 g_bqh[Cdim*32],   g_bql[Cdim*32];
__device__ __align__(16) __nv_bfloat16 g_bfh[2*Cdim*32], g_bfl[2*Cdim*32];
__device__ __align__(16) __nv_bfloat16 g_bph[Cdim*32],   g_bpl[Cdim*32];

// ---------------------------------------------------------------------------
__device__ __forceinline__ uint32_t smem_u32(const void* p) {
    uint32_t a;
    asm("{ .reg .u64 t; cvta.to.shared.u64 t, %1; cvt.u32.u64 %0, t; }" : "=r"(a) : "l"(p));
    return a;
}
__device__ __forceinline__ void cp16(uint32_t dst, const void* src) {
    asm volatile("cp.async.cg.shared.global [%0], [%1], 16;" :: "r"(dst), "l"(src));
}
__device__ __forceinline__ void cp_commit() {
    asm volatile("cp.async.commit_group;" ::: "memory");
}
__device__ __forceinline__ void ldm_x4(uint32_t& r0, uint32_t& r1, uint32_t& r2, uint32_t& r3,
                                       uint32_t addr) {
    asm volatile("ldmatrix.sync.aligned.m8n8.x4.shared.b16 {%0,%1,%2,%3}, [%4];"
                 : "=r"(r0), "=r"(r1), "=r"(r2), "=r"(r3) : "r"(addr));
}
__device__ __forceinline__ void ldm_x4t(uint32_t& r0, uint32_t& r1, uint32_t& r2, uint32_t& r3,
                                        uint32_t addr) {
    asm volatile("ldmatrix.sync.aligned.m8n8.x4.trans.shared.b16 {%0,%1,%2,%3}, [%4];"
                 : "=r"(r0), "=r"(r1), "=r"(r2), "=r"(r3) : "r"(addr));
}
__device__ __forceinline__ void mma_bf16(float* c, const uint32_t* a, const uint32_t* b) {
    asm("mma.sync.aligned.m16n8k16.row.col.f32.bf16.bf16.f32 "
        "{%0,%1,%2,%3}, {%4,%5,%6,%7}, {%8,%9}, {%0,%1,%2,%3};"
        : "+f"(c[0]), "+f"(c[1]), "+f"(c[2]), "+f"(c[3])
        : "r"(a[0]), "r"(a[1]), "r"(a[2]), "r"(a[3]), "r"(b[0]), "r"(b[1]));
}
__device__ __forceinline__ __nv_bfloat162 pack_split_hi(float v0, float v1,
                                                        __nv_bfloat16& l0, __nv_bfloat16& l1) {
    __nv_bfloat16 h0 = __float2bfloat16(v0);
    __nv_bfloat16 h1 = __float2bfloat16(v1);
    l0 = __float2bfloat16(v0 - __bfloat162float(h0));
    l1 = __float2bfloat16(v1 - __bfloat162float(h1));
    return __nv_bfloat162(h0, h1);
}

// ---------------------------------------------------------------------------
// merged fp32 -> (hi, lo) split over 5 tensors
// ---------------------------------------------------------------------------
#define SEG0 (Bsz*Tlen*Cdim/4)
#define SEG1 (SEG0 + Cdim*Cdim/4)
#define SEG2 (SEG1 + Bsz*Slen*Cdim/4)
#define SEG3 (SEG2 + 2*Cdim*Cdim/4)
#define SEG4 (SEG3 + Cdim*Cdim/4)

__global__ void __launch_bounds__(256)
split_multi(const float4* __restrict__ x,  const float4* __restrict__ Wq,
            const float4* __restrict__ ft, const float4* __restrict__ Wf,
            const float4* __restrict__ Wp,
            __nv_bfloat162* __restrict__ xhi,  __nv_bfloat162* __restrict__ xlo,
            __nv_bfloat162* __restrict__ wqhi, __nv_bfloat162* __restrict__ wqlo,
            __nv_bfloat162* __restrict__ fhi,  __nv_bfloat162* __restrict__ flo,
            __nv_bfloat162* __restrict__ wfhi, __nv_bfloat162* __restrict__ wflo,
            __nv_bfloat162* __restrict__ wphi, __nv_bfloat162* __restrict__ wplo)
{
    int gi = blockIdx.x * 256 + threadIdx.x;
    if (gi >= SEG4) return;
    const float4* in; __nv_bfloat162* hi; __nv_bfloat162* lo; int i;
    if (gi < SEG0)      { in = x;  hi = xhi;  lo = xlo;  i = gi; }
    else if (gi < SEG1) { in = Wq; hi = wqhi; lo = wqlo; i = gi - SEG0; }
    else if (gi < SEG2) { in = ft; hi = fhi;  lo = flo;  i = gi - SEG1; }
    else if (gi < SEG3) { in = Wf; hi = wfhi; lo = wflo; i = gi - SEG2; }
    else                { in = Wp; hi = wphi; lo = wplo; i = gi - SEG3; }
    float4 v = in[i];
    __nv_bfloat16 l0, l1, l2, l3;
    __nv_bfloat162 h01 = pack_split_hi(v.x, v.y, l0, l1);
    __nv_bfloat162 h23 = pack_split_hi(v.z, v.w, l2, l3);
    hi[2*i]   = h01;
    hi[2*i+1] = h23;
    lo[2*i]   = __nv_bfloat162(l0, l1);
    lo[2*i+1] = __nv_bfloat162(l2, l3);
}

__global__ void __launch_bounds__(256)
splitpad_multi(const float* __restrict__ Bq, const float* __restrict__ Bf,
               const float* __restrict__ Bp,
               __nv_bfloat16* __restrict__ qh, __nv_bfloat16* __restrict__ ql,
               __nv_bfloat16* __restrict__ fh, __nv_bfloat16* __restrict__ fl,
               __nv_bfloat16* __restrict__ ph, __nv_bfloat16* __restrict__ pl)
{
    int g = blockIdx.x * 256 + threadIdx.x;
    if (g >= 32768) return;
    int row = g >> 3;
    int j2  = (g & 7) * 2;
    const float* B; __nv_bfloat16* hi; __nv_bfloat16* lo;
    if (row < 1024)      { B = Bq; hi = qh; lo = ql; }
    else if (row < 3072) { B = Bf; hi = fh; lo = fl; row -= 1024; }
    else                 { B = Bp; hi = ph; lo = pl; row -= 3072; }
    float2 v = *reinterpret_cast<const float2*>(B + row * 16 + j2);
    __nv_bfloat16 l0, l1;
    __nv_bfloat162 h = pack_split_hi(v.x, v.y, l0, l1);
    *reinterpret_cast<__nv_bfloat162*>(hi + row * 32 + j2) = h;
    *reinterpret_cast<__nv_bfloat162*>(lo + row * 32 + j2) = __nv_bfloat162(l0, l1);
    __nv_bfloat162 z2(__float2bfloat16(0.0f), __float2bfloat16(0.0f));
    *reinterpret_cast<__nv_bfloat162*>(hi + row * 32 + 16 + j2) = z2;
    *reinterpret_cast<__nv_bfloat162*>(lo + row * 32 + 16 + j2) = z2;
}

// ---------------------------------------------------------------------------
// merged LoRA intermediates for q and f
// ---------------------------------------------------------------------------
__global__ void __launch_bounds__(256)
lora_t_merged(const float* __restrict__ x,  const float* __restrict__ Aq,
              const float* __restrict__ ft, const float* __restrict__ Af,
              __nv_bfloat16* __restrict__ tqh, __nv_bfloat16* __restrict__ tql,
              __nv_bfloat16* __restrict__ tfh, __nv_bfloat16* __restrict__ tfl,
              float scale)
{
    __shared__ float xs[64][68];
    __shared__ float as_[16][65];

    const int tid = threadIdx.x;
    const float* X; const float* Am; __nv_bfloat16 *Th, *Tl; int bm;
    if (blockIdx.x < 128) { X = x;  Am = Aq; Th = tqh; Tl = tql; bm = blockIdx.x * 64; }
    else                  { X = ft; Am = Af; Th = tfh; Tl = tfl; bm = (blockIdx.x - 128) * 64; }

    const int r  = tid & 15;
    const int mg = tid >> 4;
    float a0 = 0.f, a1 = 0.f, a2 = 0.f, a3 = 0.f;

    for (int kt = 0; kt < 1024; kt += 64) {
#pragma unroll
        for (int i = tid; i < 1024; i += 256) {
            int row = i >> 4, c4 = i & 15;
            float4 v = *reinterpret_cast<const float4*>(
                &X[(long long)(bm + row) * 1024 + kt + c4 * 4]);
            *reinterpret_cast<float4*>(&xs[row][c4 * 4]) = v;
        }
#pragma unroll
        for (int i = tid; i < 1024; i += 256) {
            int row = i >> 6, kk = i & 63;
            as_[row][kk] = Am[row * 1024 + kt + kk];
        }
        __syncthreads();
#pragma unroll 16
        for (int kk = 0; kk < 64; kk++) {
            float a = as_[r][kk];
            a0 = fmaf(xs[mg * 4 + 0][kk], a, a0);
            a1 = fmaf(xs[mg * 4 + 1][kk], a, a1);
            a2 = fmaf(xs[mg * 4 + 2][kk], a, a2);
            a3 = fmaf(xs[mg * 4 + 3][kk], a, a3);
        }
        __syncthreads();
    }
    const __nv_bfloat16 z = __float2bfloat16(0.0f);
#pragma unroll
    for (int q = 0; q < 4; q++) {
        float v = (q == 0 ? a0 : q == 1 ? a1 : q == 2 ? a2 : a3) * scale;
        long long row = bm + mg * 4 + q;
        __nv_bfloat16 h = __float2bfloat16(v);
        __nv_bfloat16 l = __float2bfloat16(v - __bfloat162float(h));
        Th[row * 32 + r] = h;       Tl[row * 32 + r] = l;
        Th[row * 32 + 16 + r] = z;  Tl[row * 32 + 16 + r] = z;
    }
}

__global__ void __launch_bounds__(256)
lora_t_split(const __nv_bfloat16* __restrict__ Xhi, const __nv_bfloat16* __restrict__ Xlo,
             const float* __restrict__ Amat,
             __nv_bfloat16* __restrict__ Thi, __nv_bfloat16* __restrict__ Tlo,
             float scale)
{
    __shared__ float xs[64][68];
    __shared__ float as_[16][65];

    const int tid = threadIdx.x;
    const int bm  = blockIdx.x * 64;
    const int r   = tid & 15;
    const int mg  = tid >> 4;

    float a0 = 0.f, a1 = 0.f, a2 = 0.f, a3 = 0.f;

    for (int kt = 0; kt < 1024; kt += 64) {
#pragma unroll
        for (int i = tid; i < 1024; i += 256) {
            int row = i >> 4, c4 = i & 15;
            long long base = (long long)(bm + row) * 1024 + kt + c4 * 4;
            uint2 vh = *reinterpret_cast<const uint2*>(Xhi + base);
            uint2 vl = *reinterpret_cast<const uint2*>(Xlo + base);
            __nv_bfloat162 h0 = *reinterpret_cast<__nv_bfloat162*>(&vh.x);
            __nv_bfloat162 h1 = *reinterpret_cast<__nv_bfloat162*>(&vh.y);
            __nv_bfloat162 l0 = *reinterpret_cast<__nv_bfloat162*>(&vl.x);
            __nv_bfloat162 l1 = *reinterpret_cast<__nv_bfloat162*>(&vl.y);
            xs[row][c4*4+0] = __bfloat162float(h0.x) + __bfloat162float(l0.x);
            xs[row][c4*4+1] = __bfloat162float(h0.y) + __bfloat162float(l0.y);
            xs[row][c4*4+2] = __bfloat162float(h1.x) + __bfloat162float(l1.x);
            xs[row][c4*4+3] = __bfloat162float(h1.y) + __bfloat162float(l1.y);
        }
#pragma unroll
        for (int i = tid; i < 1024; i += 256) {
            int row = i >> 6, kk = i & 63;
            as_[row][kk] = Amat[row * 1024 + kt + kk];
        }
        __syncthreads();
#pragma unroll 16
        for (int kk = 0; kk < 64; kk++) {
            float a = as_[r][kk];
            a0 = fmaf(xs[mg * 4 + 0][kk], a, a0);
            a1 = fmaf(xs[mg * 4 + 1][kk], a, a1);
            a2 = fmaf(xs[mg * 4 + 2][kk], a, a2);
            a3 = fmaf(xs[mg * 4 + 3][kk], a, a3);
        }
        __syncthreads();
    }
    const __nv_bfloat16 z = __float2bfloat16(0.0f);
#pragma unroll
    for (int q = 0; q < 4; q++) {
        float v = (q == 0 ? a0 : q == 1 ? a1 : q == 2 ? a2 : a3) * scale;
        long long row = bm + mg * 4 + q;
        __nv_bfloat16 h = __float2bfloat16(v);
        __nv_bfloat16 l = __float2bfloat16(v - __bfloat162float(h));
        Thi[row * 32 + r] = h;       Tlo[row * 32 + r] = l;
        Thi[row * 32 + 16 + r] = z;  Tlo[row * 32 + 16 + r] = z;
    }
}

// ---------------------------------------------------------------------------
// split-bf16 mma.sync GEMM body, 3-stage pipeline, warp tile 64x32
// ---------------------------------------------------------------------------
#define MG_STAGE 32768
#define MG_SMEM  (3 * MG_STAGE)

template<bool SPLIT_OUT>
__device__ __forceinline__ void
gemm_body(int bm, int bn,
          const __nv_bfloat16* __restrict__ Ahi, const __nv_bfloat16* __restrict__ Alo,
          const __nv_bfloat16* __restrict__ Bhi, const __nv_bfloat16* __restrict__ Blo,
          const __nv_bfloat16* __restrict__ LThi, const __nv_bfloat16* __restrict__ LTlo,
          const __nv_bfloat16* __restrict__ LBhi, const __nv_bfloat16* __restrict__ LBlo,
          float* __restrict__ C, __nv_bfloat16* __restrict__ Chi,
          __nv_bfloat16* __restrict__ Clo,
          int K, int N, const float* __restrict__ bias)
{
    extern __shared__ char smem[];
    const uint32_t sb = smem_u32(smem);
    const int tid  = threadIdx.x;
    const int lane = tid & 31;
    const int warp = tid >> 5;
    const int wm   = warp >> 2;   // 0..1 -> 64-row slice
    const int wn   = warp & 3;    // 0..3 -> 32-col slice

    const int KCH = K >> 5;
    const int NC  = KCH + 1;

    float acc[4][4][4];
#pragma unroll
    for (int m = 0; m < 4; m++)
#pragma unroll
        for (int n = 0; n < 4; n++)
#pragma unroll
            for (int j = 0; j < 4; j++) acc[m][n][j] = 0.0f;

    auto load_chunk = [&](int ch, int st) {
        const bool lora = (ch == KCH);
        const int kt = ch << 5;
#pragma unroll
        for (int i = tid; i < 2048; i += 256) {
            int tile = i >> 9;
            int idx  = i & 511;
            int row  = idx >> 2;
            int c4   = idx & 3;
            const __nv_bfloat16* g;
            long long off;
            if (!lora) {
                g = (tile == 0) ? Ahi : (tile == 1) ? Alo : (tile == 2) ? Bhi : Blo;
                int r0 = (tile < 2) ? bm : bn;
                off = (long long)(r0 + row) * K + kt + c4 * 8;
            } else {
                g = (tile == 0) ? LThi : (tile == 1) ? LTlo : (tile == 2) ? LBhi : LBlo;
                int r0 = (tile < 2) ? bm : bn;
                off = (long long)(r0 + row) * 32 + c4 * 8;
            }
            uint32_t dst = sb + st * MG_STAGE + tile * 8192 + row * 64
                         + ((c4 ^ ((row >> 1) & 3)) << 4);
            cp16(dst, g + off);
        }
        cp_commit();
    };

    load_chunk(0, 0);
    load_chunk(1, 1);

    for (int ch = 0; ch < NC; ch++) {
        const int st = ch % 3;
        if (ch + 2 < NC) {
            load_chunk(ch + 2, (ch + 2) % 3);
            asm volatile("cp.async.wait_group 2;" ::: "memory");
        } else if (ch + 1 < NC) {
            asm volatile("cp.async.wait_group 1;" ::: "memory");
        } else {
            asm volatile("cp.async.wait_group 0;" ::: "memory");
        }
        __syncthreads();

        const uint32_t stb = sb + st * MG_STAGE;
#pragma unroll
        for (int kk = 0; kk < 2; kk++) {
            // A fragments: 64 rows (4 x m16), hi + lo
            uint32_t ah[4][4], al[4][4];
#pragma unroll
            for (int mf = 0; mf < 4; mf++) {
                int row = wm * 64 + mf * 16 + (lane & 15);
                int c4  = kk * 2 + (lane >> 4);
                uint32_t sw = (uint32_t)((c4 ^ ((row >> 1) & 3)) << 4);
                uint32_t ad = stb + row * 64 + sw;
                ldm_x4(ah[mf][0], ah[mf][1], ah[mf][2], ah[mf][3], ad);
                ldm_x4(al[mf][0], al[mf][1], al[mf][2], al[mf][3], ad + 8192);
            }
            // B fragments: 32 cols (4 x n8), hi + lo
            uint32_t bh[4][2], bl[4][2];
#pragma unroll
            for (int p = 0; p < 2; p++) {
                int row = wn * 32 + p * 16 + (lane & 15);
                int c4  = kk * 2 + (lane >> 4);
                uint32_t sw = (uint32_t)((c4 ^ ((row >> 1) & 3)) << 4);
                uint32_t ad = stb + 16384 + row * 64 + sw;
                uint32_t r0, r1, r2, r3;
                ldm_x4(r0, r1, r2, r3, ad);
                bh[2*p][0] = r0; bh[2*p][1] = r2;
                bh[2*p+1][0] = r1; bh[2*p+1][1] = r3;
                ldm_x4(r0, r1, r2, r3, ad + 8192);
                bl[2*p][0] = r0; bl[2*p][1] = r2;
                bl[2*p+1][0] = r1; bl[2*p+1][1] = r3;
            }
#pragma unroll
            for (int mf = 0; mf < 4; mf++)
#pragma unroll
                for (int n = 0; n < 4; n++)
                    mma_bf16(acc[mf][n], ah[mf], bh[n]);
#pragma unroll
            for (int mf = 0; mf < 4; mf++)
#pragma unroll
                for (int n = 0; n < 4; n++)
                    mma_bf16(acc[mf][n], ah[mf], bl[n]);
#pragma unroll
            for (int mf = 0; mf < 4; mf++)
#pragma unroll
                for (int n = 0; n < 4; n++)
                    mma_bf16(acc[mf][n], al[mf], bh[n]);
        }
        __syncthreads();
    }

#pragma unroll
    for (int mf = 0; mf < 4; mf++) {
        int r1 = bm + wm * 64 + mf * 16 + (lane >> 2);
#pragma unroll
        for (int n = 0; n < 4; n++) {
            int col = bn + wn * 32 + n * 8 + (lane & 3) * 2;
            float b0 = bias[col], b1 = bias[col + 1];
            float v00 = acc[mf][n][0] + b0, v01 = acc[mf][n][1] + b1;
            float v10 = acc[mf][n][2] + b0, v11 = acc[mf][n][3] + b1;
            if (SPLIT_OUT) {
                __nv_bfloat16 l0, l1;
                __nv_bfloat162 h = pack_split_hi(v00, v01, l0, l1);
                *reinterpret_cast<__nv_bfloat162*>(&Chi[(long long)r1 * N + col]) = h;
                *reinterpret_cast<__nv_bfloat162*>(&Clo[(long long)r1 * N + col]) =
                    __nv_bfloat162(l0, l1);
                h = pack_split_hi(v10, v11, l0, l1);
                *reinterpret_cast<__nv_bfloat162*>(&Chi[(long long)(r1 + 8) * N + col]) = h;
                *reinterpret_cast<__nv_bfloat162*>(&Clo[(long long)(r1 + 8) * N + col]) =
                    __nv_bfloat162(l0, l1);
            } else {
                *reinterpret_cast<float2*>(&C[(long long)r1 * N + col]) =
                    make_float2(v00, v01);
                *reinterpret_cast<float2*>(&C[(long long)(r1 + 8) * N + col]) =
                    make_float2(v10, v11);
            }
        }
    }
}

__global__ void __launch_bounds__(256, 2)
mma_gemm_out(const __nv_bfloat16* __restrict__ Ahi, const __nv_bfloat16* __restrict__ Alo,
             const __nv_bfloat16* __restrict__ Bhi, const __nv_bfloat16* __restrict__ Blo,
             const __nv_bfloat16* __restrict__ LThi, const __nv_bfloat16* __restrict__ LTlo,
             const __nv_bfloat16* __restrict__ LBhi, const __nv_bfloat16* __restrict__ LBlo,
             float* __restrict__ C, const float* __restrict__ bias)
{
    gemm_body<false>(blockIdx.y * 128, blockIdx.x * 128,
                     Ahi, Alo, Bhi, Blo, LThi, LTlo, LBhi, LBlo,
                     C, nullptr, nullptr, 1024, 1024, bias);
}

__global__ void __launch_bounds__(256, 2)
mma_gemm_qkv(const __nv_bfloat16* __restrict__ xhi, const __nv_bfloat16* __restrict__ xlo,
             const __nv_bfloat16* __restrict__ wqhi, const __nv_bfloat16* __restrict__ wqlo,
             const __nv_bfloat16* __restrict__ tqh, const __nv_bfloat16* __restrict__ tql,
             const __nv_bfloat16* __restrict__ bqh, const __nv_bfloat16* __restrict__ bql,
             __nv_bfloat16* __restrict__ qh, __nv_bfloat16* __restrict__ ql,
             const float* __restrict__ bq,
             const __nv_bfloat16* __restrict__ fhi, const __nv_bfloat16* __restrict__ flo,
             const __nv_bfloat16* __restrict__ wfhi, const __nv_bfloat16* __restrict__ wflo,
             const __nv_bfloat16* __restrict__ tfh, const __nv_bfloat16* __restrict__ tfl,
             const __nv_bfloat16* __restrict__ bfh, const __nv_bfloat16* __restrict__ bfl,
             __nv_bfloat16* __restrict__ kvh, __nv_bfloat16* __restrict__ kvl,
             const float* __restrict__ bfv)
{
    int bid = blockIdx.x;
    if (bid < 512) {
        gemm_body<true>((bid >> 3) * 128, (bid & 7) * 128,
                        xhi, xlo, wqhi, wqlo, tqh, tql, bqh, bql,
                        nullptr, qh, ql, 1024, 1024, bq);
    } else {
        int r = bid - 512;
        gemm_body<true>((r >> 4) * 128, (r & 15) * 128,
                        fhi, flo, wfhi, wflo, tfh, tfl, bfh, bfl,
                        nullptr, kvh, kvl, 1024, 2048, bfv);
    }
}

// ---------------------------------------------------------------------------
// Persistent fused attention (256 threads) — unchanged from R8
// ---------------------------------------------------------------------------
#define FA_KH   0
#define FA_KL   32768
#define FA_VH   65536
#define FA_VL   98304
#define FA_QH   131072
#define FA_QL   139264
#define FA_PH   147456
#define FA_PL   180224
#define FA_REDM 212992
#define FA_REDS 214016
#define FA_SMEM 215040

__global__ void __launch_bounds__(256)
fa_kernel(const __nv_bfloat16* __restrict__ Qh, const __nv_bfloat16* __restrict__ Ql,
          const __nv_bfloat16* __restrict__ KVh, const __nv_bfloat16* __restrict__ KVl,
          __nv_bfloat16* __restrict__ Yh, __nv_bfloat16* __restrict__ Yl)
{
    extern __shared__ char smem[];
    const uint32_t sb = smem_u32(smem);
    const int tid  = threadIdx.x;
    const int lane = tid & 31;
    const int warp = tid >> 5;
    const int bh = blockIdx.x;
    const int b = bh >> 4, h = bh & 15;

    const int rq = lane >> 2, cq = lane & 3;
    const int wm = warp >> 2;
    const int wn = warp & 3;

    float* red_max = reinterpret_cast<float*>(smem + FA_REDM);
    float* red_sum = reinterpret_cast<float*>(smem + FA_REDS);

    {
        const long long kbase = ((long long)(b * 256)) * 2048 + h * 64;
#pragma unroll
        for (int i = tid; i < 2048; i += 256) {
            int row = i >> 3, c = i & 7;
            uint32_t sw = (uint32_t)((c ^ (row & 7)) << 4);
            long long go = (long long)row * 2048 + c * 8;
            cp16(sb + FA_KH + row * 128 + sw, KVh + kbase + go);
            cp16(sb + FA_KL + row * 128 + sw, KVl + kbase + go);
            cp16(sb + FA_VH + row * 128 + sw, KVh + kbase + 1024 + go);
            cp16(sb + FA_VL + row * 128 + sw, KVl + kbase + 1024 + go);
        }
        cp_commit();
        asm volatile("cp.async.wait_group 0;" ::: "memory");
        __syncthreads();
    }

    for (int tt = 0; tt < 16; tt++) {
        const int t0 = tt * 64;
        const bool need_mask = (t0 < Slen);
        const int tmax = t0 + 63;

        {
            const long long qbase = ((long long)(b * 1024 + t0)) * 1024 + h * 64;
#pragma unroll
            for (int i = tid; i < 512; i += 256) {
                int row = i >> 3, c = i & 7;
                uint32_t sw = (uint32_t)((c ^ (row & 7)) << 4);
                cp16(sb + FA_QH + row * 128 + sw, Qh + qbase + (long long)row * 1024 + c * 8);
                cp16(sb + FA_QL + row * 128 + sw, Ql + qbase + (long long)row * 1024 + c * 8);
            }
            cp_commit();
            asm volatile("cp.async.wait_group 0;" ::: "memory");
            __syncthreads();
        }

        float acc[2][8][4];
#pragma unroll
        for (int m = 0; m < 2; m++)
#pragma unroll
            for (int n = 0; n < 8; n++)
#pragma unroll
                for (int j = 0; j < 4; j++) acc[m][n][j] = 0.0f;

#pragma unroll
        for (int ks = 0; ks < 4; ks++) {
            uint32_t ah[2][4], al[2][4];
#pragma unroll
            for (int mf = 0; mf < 2; mf++) {
                int row = wm * 32 + mf * 16 + (lane & 15);
                int ch  = ks * 2 + (lane >> 4);
                uint32_t ad = sb + FA_QH + row * 128 + (uint32_t)((ch ^ (row & 7)) << 4);
                ldm_x4(ah[mf][0], ah[mf][1], ah[mf][2], ah[mf][3], ad);
                ldm_x4(al[mf][0], al[mf][1], al[mf][2], al[mf][3], ad + 8192);
            }
            uint32_t bh_[8][2], bl_[8][2];
#pragma unroll
            for (int p = 0; p < 4; p++) {
                if (need_mask && (wn * 64 + p * 16) > tmax) continue;
                int row = wn * 64 + p * 16 + (lane & 15);
                int ch  = ks * 2 + (lane >> 4);
                uint32_t ad = sb + FA_KH + row * 128 + (uint32_t)((ch ^ (row & 7)) << 4);
                uint32_t r0, r1, r2, r3;
                ldm_x4(r0, r1, r2, r3, ad);
                bh_[2*p][0] = r0; bh_[2*p][1] = r2;
                bh_[2*p+1][0] = r1; bh_[2*p+1][1] = r3;
                ldm_x4(r0, r1, r2, r3, ad + 32768);
                bl_[2*p][0] = r0; bl_[2*p][1] = r2;
                bl_[2*p+1][0] = r1; bl_[2*p+1][1] = r3;
            }
#pragma unroll
            for (int mf = 0; mf < 2; mf++)
#pragma unroll
                for (int n = 0; n < 8; n++) {
                    if (need_mask && (wn * 64 + n * 8) > tmax) continue;
                    mma_bf16(acc[mf][n], ah[mf], bh_[n]);
                }
#pragma unroll
            for (int mf = 0; mf < 2; mf++)
#pragma unroll
                for (int n = 0; n < 8; n++) {
                    if (need_mask && (wn * 64 + n * 8) > tmax) continue;
                    mma_bf16(acc[mf][n], ah[mf], bl_[n]);
                }
#pragma unroll
            for (int mf = 0; mf < 2; mf++)
#pragma unroll
                for (int n = 0; n < 8; n++) {
                    if (need_mask && (wn * 64 + n * 8) > tmax) continue;
                    mma_bf16(acc[mf][n], al[mf], bh_[n]);
                }
        }

#pragma unroll
        for (int mf = 0; mf < 2; mf++)
#pragma unroll
            for (int sub = 0; sub < 2; sub++) {
                int rl = wm * 32 + mf * 16 + sub * 8 + rq;
                int trow = t0 + rl;
                float m = -1e30f;
#pragma unroll
                for (int nf = 0; nf < 8; nf++) {
                    int col = wn * 64 + nf * 8 + cq * 2;
                    float v0 = acc[mf][nf][sub*2]     * 0.125f;
                    float v1 = acc[mf][nf][sub*2 + 1] * 0.125f;
                    if (need_mask) {
                        if (col     > trow) v0 = -1e30f;
                        if (col + 1 > trow) v1 = -1e30f;
                    }
                    acc[mf][nf][sub*2]     = v0;
                    acc[mf][nf][sub*2 + 1] = v1;
                    m = fmaxf(m, fmaxf(v0, v1));
                }
                m = fmaxf(m, __shfl_xor_sync(0xffffffffu, m, 1));
                m = fmaxf(m, __shfl_xor_sync(0xffffffffu, m, 2));
                if (cq == 0) red_max[wn * 64 + rl] = m;
            }
        __syncthreads();

#pragma unroll
        for (int mf = 0; mf < 2; mf++)
#pragma unroll
            for (int sub = 0; sub < 2; sub++) {
                int rl = wm * 32 + mf * 16 + sub * 8 + rq;
                float M = fmaxf(fmaxf(red_max[rl], red_max[64 + rl]),
                                fmaxf(red_max[128 + rl], red_max[192 + rl]));
                float s = 0.0f;
#pragma unroll
                for (int nf = 0; nf < 8; nf++) {
                    float e0 = __expf(acc[mf][nf][sub*2]     - M);
                    float e1 = __expf(acc[mf][nf][sub*2 + 1] - M);
                    acc[mf][nf][sub*2]     = e0;
                    acc[mf][nf][sub*2 + 1] = e1;
                    s += e0 + e1;
                }
                s += __shfl_xor_sync(0xffffffffu, s, 1);
                s += __shfl_xor_sync(0xffffffffu, s, 2);
                if (cq == 0) red_sum[wn * 64 + rl] = s;
            }
        __syncthreads();

#pragma unroll
        for (int mf = 0; mf < 2; mf++)
#pragma unroll
            for (int sub = 0; sub < 2; sub++) {
                int rl = wm * 32 + mf * 16 + sub * 8 + rq;
#pragma unroll
                for (int nf = 0; nf < 8; nf++) {
                    int col = wn * 64 + nf * 8 + cq * 2;
                    __nv_bfloat16 l0, l1;
                    __nv_bfloat162 hh = pack_split_hi(acc[mf][nf][sub*2],
                                                      acc[mf][nf][sub*2 + 1], l0, l1);
                    int chnk = col >> 3;
                    uint32_t off = (uint32_t)(rl * 512 + ((chnk ^ (rl & 7)) << 4) + (col & 7) * 2);
                    *reinterpret_cast<__nv_bfloat162*>(smem + FA_PH + off) = hh;
                    *reinterpret_cast<__nv_bfloat162*>(smem + FA_PL + off) =
                        __nv_bfloat162(l0, l1);
                }
            }
        __syncthreads();

        const int nks = need_mask ? ((tmax >> 4) + 1) : 16;
        float acc2[2][2][4];
#pragma unroll
        for (int m = 0; m < 2; m++)
#pragma unroll
            for (int n = 0; n < 2; n++)
#pragma unroll
                for (int j = 0; j < 4; j++) acc2[m][n][j] = 0.0f;

        for (int ks = 0; ks < nks; ks++) {
            uint32_t ph[2][4], pl[2][4];
#pragma unroll
            for (int mf = 0; mf < 2; mf++) {
                int row = wm * 32 + mf * 16 + (lane & 15);
                int ch  = ks * 2 + (lane >> 4);
                uint32_t ad = sb + FA_PH + row * 512 + (uint32_t)((ch ^ (row & 7)) << 4);
                ldm_x4(ph[mf][0], ph[mf][1], ph[mf][2], ph[mf][3], ad);
                ldm_x4(pl[mf][0], pl[mf][1], pl[mf][2], pl[mf][3], ad + 32768);
            }
            uint32_t vh_[2][2], vl_[2][2];
            {
                int g = lane >> 3;
                int srow = ks * 16 + (g & 1) * 8 + (lane & 7);
                int dch  = wn * 2 + (g >> 1);
                uint32_t ad = sb + FA_VH + srow * 128 + (uint32_t)((dch ^ (srow & 7)) << 4);
                uint32_t r0, r1, r2, r3;
                ldm_x4t(r0, r1, r2, r3, ad);
                vh_[0][0] = r0; vh_[0][1] = r1; vh_[1][0] = r2; vh_[1][1] = r3;
                ldm_x4t(r0, r1, r2, r3, ad + 32768);
                vl_[0][0] = r0; vl_[0][1] = r1; vl_[1][0] = r2; vl_[1][1] = r3;
            }
#pragma unroll
            for (int mf = 0; mf < 2; mf++)
#pragma unroll
                for (int nf = 0; nf < 2; nf++)
                    mma_bf16(acc2[mf][nf], ph[mf], vh_[nf]);
#pragma unroll
            for (int mf = 0; mf < 2; mf++)
#pragma unroll
                for (int nf = 0; nf < 2; nf++)
                    mma_bf16(acc2[mf][nf], ph[mf], vl_[nf]);
#pragma unroll
            for (int mf = 0; mf < 2; mf++)
#pragma unroll
                for (int nf = 0; nf < 2; nf++)
                    mma_bf16(acc2[mf][nf], pl[mf], vh_[nf]);
        }

#pragma unroll
        for (int mf = 0; mf < 2; mf++)
#pragma unroll
            for (int sub = 0; sub < 2; sub++) {
                int rl = wm * 32 + mf * 16 + sub * 8 + rq;
                float inv = 1.0f / (red_sum[rl] + red_sum[64 + rl] +
                                    red_sum[128 + rl] + red_sum[192 + rl]);
                long long yo = ((long long)(b * 1024 + t0 + rl)) * 1024 + h * 64;
#pragma unroll
                for (int nf = 0; nf < 2; nf++) {
                    int col = wn * 16 + nf * 8 + cq * 2;
                    float v0 = acc2[mf][nf][sub*2]     * inv;
                    float v1 = acc2[mf][nf][sub*2 + 1] * inv;
                    __nv_bfloat16 l0, l1;
                    __nv_bfloat162 hh = pack_split_hi(v0, v1, l0, l1);
                    *reinterpret_cast<__nv_bfloat162*>(&Yh[yo + col]) = hh;
                    *reinterpret_cast<__nv_bfloat162*>(&Yl[yo + col]) = __nv_bfloat162(l0, l1);
                }
            }
        __syncthreads();
    }
}

// ---------------------------------------------------------------------------
// Launch
// ---------------------------------------------------------------------------
extern "C" void kernel_launch(void* const* d_in, const int* in_sizes, int n_in,
                              void* d_out, int out_size)
{
    const float* x  = (const float*)d_in[0];
    const float* ft = (const float*)d_in[1];
    const float* Wq = (const float*)d_in[2];
    const float* bq = (const float*)d_in[3];
    const float* Aq = (const float*)d_in[4];
    const float* Bq = (const float*)d_in[5];
    const float* Wf = (const float*)d_in[6];
    const float* bfv= (const float*)d_in[7];
    const float* Af = (const float*)d_in[8];
    const float* Bf = (const float*)d_in[9];
    const float* Wp = (const float*)d_in[10];
    const float* bp = (const float*)d_in[11];
    const float* Ap = (const float*)d_in[12];
    const float* Bp = (const float*)d_in[13];
    float* out = (float*)d_out;

    __nv_bfloat16 *xhi, *xlo, *fhi, *flo, *yhi, *ylo;
    __nv_bfloat16 *wqhi, *wqlo, *wfhi, *wflo, *wphi, *wplo;
    __nv_bfloat16 *qh, *ql, *kvh, *kvl;
    __nv_bfloat16 *tqh, *tql, *tfh, *tfl, *tph, *tpl;
    __nv_bfloat16 *bqh, *bql, *bfh, *bfl, *bph, *bpl;
    cudaGetSymbolAddress((void**)&xhi, g_xhi);  cudaGetSymbolAddress((void**)&xlo, g_xlo);
    cudaGetSymbolAddress((void**)&fhi, g_fhi);  cudaGetSymbolAddress((void**)&flo, g_flo);
    cudaGetSymbolAddress((void**)&yhi, g_yhi);  cudaGetSymbolAddress((void**)&ylo, g_ylo);
    cudaGetSymbolAddress((void**)&wqhi, g_wqhi); cudaGetSymbolAddress((void**)&wqlo, g_wqlo);
    cudaGetSymbolAddress((void**)&wfhi, g_wfhi); cudaGetSymbolAddress((void**)&wflo, g_wflo);
    cudaGetSymbolAddress((void**)&wphi, g_wphi); cudaGetSymbolAddress((void**)&wplo, g_wplo);
    cudaGetSymbolAddress((void**)&qh, g_qh);    cudaGetSymbolAddress((void**)&ql, g_ql);
    cudaGetSymbolAddress((void**)&kvh, g_kvh);  cudaGetSymbolAddress((void**)&kvl, g_kvl);
    cudaGetSymbolAddress((void**)&tqh, g_tqh);  cudaGetSymbolAddress((void**)&tql, g_tql);
    cudaGetSymbolAddress((void**)&tfh, g_tfh);  cudaGetSymbolAddress((void**)&tfl, g_tfl);
    cudaGetSymbolAddress((void**)&tph, g_tph);  cudaGetSymbolAddress((void**)&tpl, g_tpl);
    cudaGetSymbolAddress((void**)&bqh, g_bqh);  cudaGetSymbolAddress((void**)&bql, g_bql);
    cudaGetSymbolAddress((void**)&bfh, g_bfh);  cudaGetSymbolAddress((void**)&bfl, g_bfl);
    cudaGetSymbolAddress((void**)&bph, g_bph);  cudaGetSymbolAddress((void**)&bpl, g_bpl);

    cudaFuncSetAttribute(mma_gemm_out, cudaFuncAttributeMaxDynamicSharedMemorySize, MG_SMEM);
    cudaFuncSetAttribute(mma_gemm_qkv, cudaFuncAttributeMaxDynamicSharedMemorySize, MG_SMEM);
    cudaFuncSetAttribute(fa_kernel, cudaFuncAttributeMaxDynamicSharedMemorySize, FA_SMEM);

    const float SC = 1.0f / 16.0f;

    split_multi<<<(SEG4 + 255)/256, 256>>>(
        (const float4*)x, (const float4*)Wq, (const float4*)ft,
        (const float4*)Wf, (const float4*)Wp,
        (__nv_bfloat162*)xhi,  (__nv_bfloat162*)xlo,
        (__nv_bfloat162*)wqhi, (__nv_bfloat162*)wqlo,
        (__nv_bfloat162*)fhi,  (__nv_bfloat162*)flo,
        (__nv_bfloat162*)wfhi, (__nv_bfloat162*)wflo,
        (__nv_bfloat162*)wphi, (__nv_bfloat162*)wplo);

    lora_t_merged<<<160, 256>>>(x, Aq, ft, Af, tqh, tql, tfh, tfl, SC);
    splitpad_multi<<<128, 256>>>(Bq, Bf, Bp, bqh, bql, bfh, bfl, bph, bpl);

    mma_gemm_qkv<<<768, 256, MG_SMEM>>>(
        xhi, xlo, wqhi, wqlo, tqh, tql, bqh, bql, qh, ql, bq,
        fhi, flo, wfhi, wflo, tfh, tfl, bfh, bfl, kvh, kvl, bfv);

    fa_kernel<<<128, 256, FA_SMEM>>>(qh, ql, kvh, kvl, yhi, ylo);

    lora_t_split<<<128, 256>>>(yhi, ylo, Ap, tph, tpl, SC);

    mma_gemm_out<<<dim3(8, 64), 256, MG_SMEM>>>(yhi, ylo, wphi, wplo,
        tph, tpl, bph, bpl, out, bp);
}

// round 16
// speedup vs baseline: 1.5497x; 1.5497x over previous
#include <cuda_runtime.h>
#include <cuda_bf16.h>
#include <math.h>
#include <stdint.h>

// ---------------------------------------------------------------------------
// CrossAttention with LoRA — round 12 (R11 with call-site fix)
// gemm 32x64 warp tile + separate Q/KV launches; fa Q double-buffer prefetch
// B=8, T=1024, S=256, C=1024, H=16, D=64, R=16, SCALING=1/16
// ---------------------------------------------------------------------------

#define Bsz   8
#define Tlen  1024
#define Slen  256
#define Cdim  1024

__device__ __align__(16) __nv_bfloat16 g_xhi[Bsz*Tlen*Cdim], g_xlo[Bsz*Tlen*Cdim];
__device__ __align__(16) __nv_bfloat16 g_fhi[Bsz*Slen*Cdim], g_flo[Bsz*Slen*Cdim];
__device__ __align__(16) __nv_bfloat16 g_yhi[Bsz*Tlen*Cdim], g_ylo[Bsz*Tlen*Cdim];
__device__ __align__(16) __nv_bfloat16 g_wqhi[Cdim*Cdim],   g_wqlo[Cdim*Cdim];
__device__ __align__(16) __nv_bfloat16 g_wfhi[2*Cdim*Cdim], g_wflo[2*Cdim*Cdim];
__device__ __align__(16) __nv_bfloat16 g_wphi[Cdim*Cdim],   g_wplo[Cdim*Cdim];

__device__ __align__(16) __nv_bfloat16 g_qh[Bsz*Tlen*Cdim],     g_ql[Bsz*Tlen*Cdim];
__device__ __align__(16) __nv_bfloat16 g_kvh[Bsz*Slen*2*Cdim],  g_kvl[Bsz*Slen*2*Cdim];

__device__ __align__(16) __nv_bfloat16 g_tqh[Bsz*Tlen*32], g_tql[Bsz*Tlen*32];
__device__ __align__(16) __nv_bfloat16 g_tfh[Bsz*Slen*32], g_tfl[Bsz*Slen*32];
__device__ __align__(16) __nv_bfloat16 g_tph[Bsz*Tlen*32], g_tpl[Bsz*Tlen*32];
__device__ __align__(16) __nv_bfloat16 g_bqh[Cdim*32],   g_bql[Cdim*32];
__device__ __align__(16) __nv_bfloat16 g_bfh[2*Cdim*32], g_bfl[2*Cdim*32];
__device__ __align__(16) __nv_bfloat16 g_bph[Cdim*32],   g_bpl[Cdim*32];

// ---------------------------------------------------------------------------
__device__ __forceinline__ uint32_t smem_u32(const void* p) {
    uint32_t a;
    asm("{ .reg .u64 t; cvta.to.shared.u64 t, %1; cvt.u32.u64 %0, t; }" : "=r"(a) : "l"(p));
    return a;
}
__device__ __forceinline__ void cp16(uint32_t dst, const void* src) {
    asm volatile("cp.async.cg.shared.global [%0], [%1], 16;" :: "r"(dst), "l"(src));
}
__device__ __forceinline__ void cp_commit() {
    asm volatile("cp.async.commit_group;" ::: "memory");
}
__device__ __forceinline__ void ldm_x4(uint32_t& r0, uint32_t& r1, uint32_t& r2, uint32_t& r3,
                                       uint32_t addr) {
    asm volatile("ldmatrix.sync.aligned.m8n8.x4.shared.b16 {%0,%1,%2,%3}, [%4];"
                 : "=r"(r0), "=r"(r1), "=r"(r2), "=r"(r3) : "r"(addr));
}
__device__ __forceinline__ void ldm_x4t(uint32_t& r0, uint32_t& r1, uint32_t& r2, uint32_t& r3,
                                        uint32_t addr) {
    asm volatile("ldmatrix.sync.aligned.m8n8.x4.trans.shared.b16 {%0,%1,%2,%3}, [%4];"
                 : "=r"(r0), "=r"(r1), "=r"(r2), "=r"(r3) : "r"(addr));
}
__device__ __forceinline__ void mma_bf16(float* c, const uint32_t* a, const uint32_t* b) {
    asm("mma.sync.aligned.m16n8k16.row.col.f32.bf16.bf16.f32 "
        "{%0,%1,%2,%3}, {%4,%5,%6,%7}, {%8,%9}, {%0,%1,%2,%3};"
        : "+f"(c[0]), "+f"(c[1]), "+f"(c[2]), "+f"(c[3])
        : "r"(a[0]), "r"(a[1]), "r"(a[2]), "r"(a[3]), "r"(b[0]), "r"(b[1]));
}
__device__ __forceinline__ __nv_bfloat162 pack_split_hi(float v0, float v1,
                                                        __nv_bfloat16& l0, __nv_bfloat16& l1) {
    __nv_bfloat16 h0 = __float2bfloat16(v0);
    __nv_bfloat16 h1 = __float2bfloat16(v1);
    l0 = __float2bfloat16(v0 - __bfloat162float(h0));
    l1 = __float2bfloat16(v1 - __bfloat162float(h1));
    return __nv_bfloat162(h0, h1);
}

// ---------------------------------------------------------------------------
// merged fp32 -> (hi, lo) split over 5 tensors
// ---------------------------------------------------------------------------
#define SEG0 (Bsz*Tlen*Cdim/4)
#define SEG1 (SEG0 + Cdim*Cdim/4)
#define SEG2 (SEG1 + Bsz*Slen*Cdim/4)
#define SEG3 (SEG2 + 2*Cdim*Cdim/4)
#define SEG4 (SEG3 + Cdim*Cdim/4)

__global__ void __launch_bounds__(256)
split_multi(const float4* __restrict__ x,  const float4* __restrict__ Wq,
            const float4* __restrict__ ft, const float4* __restrict__ Wf,
            const float4* __restrict__ Wp,
            __nv_bfloat162* __restrict__ xhi,  __nv_bfloat162* __restrict__ xlo,
            __nv_bfloat162* __restrict__ wqhi, __nv_bfloat162* __restrict__ wqlo,
            __nv_bfloat162* __restrict__ fhi,  __nv_bfloat162* __restrict__ flo,
            __nv_bfloat162* __restrict__ wfhi, __nv_bfloat162* __restrict__ wflo,
            __nv_bfloat162* __restrict__ wphi, __nv_bfloat162* __restrict__ wplo)
{
    int gi = blockIdx.x * 256 + threadIdx.x;
    if (gi >= SEG4) return;
    const float4* in; __nv_bfloat162* hi; __nv_bfloat162* lo; int i;
    if (gi < SEG0)      { in = x;  hi = xhi;  lo = xlo;  i = gi; }
    else if (gi < SEG1) { in = Wq; hi = wqhi; lo = wqlo; i = gi - SEG0; }
    else if (gi < SEG2) { in = ft; hi = fhi;  lo = flo;  i = gi - SEG1; }
    else if (gi < SEG3) { in = Wf; hi = wfhi; lo = wflo; i = gi - SEG2; }
    else                { in = Wp; hi = wphi; lo = wplo; i = gi - SEG3; }
    float4 v = in[i];
    __nv_bfloat16 l0, l1, l2, l3;
    __nv_bfloat162 h01 = pack_split_hi(v.x, v.y, l0, l1);
    __nv_bfloat162 h23 = pack_split_hi(v.z, v.w, l2, l3);
    hi[2*i]   = h01;
    hi[2*i+1] = h23;
    lo[2*i]   = __nv_bfloat162(l0, l1);
    lo[2*i+1] = __nv_bfloat162(l2, l3);
}

__global__ void __launch_bounds__(256)
splitpad_multi(const float* __restrict__ Bq, const float* __restrict__ Bf,
               const float* __restrict__ Bp,
               __nv_bfloat16* __restrict__ qh, __nv_bfloat16* __restrict__ ql,
               __nv_bfloat16* __restrict__ fh, __nv_bfloat16* __restrict__ fl,
               __nv_bfloat16* __restrict__ ph, __nv_bfloat16* __restrict__ pl)
{
    int g = blockIdx.x * 256 + threadIdx.x;
    if (g >= 32768) return;
    int row = g >> 3;
    int j2  = (g & 7) * 2;
    const float* B; __nv_bfloat16* hi; __nv_bfloat16* lo;
    if (row < 1024)      { B = Bq; hi = qh; lo = ql; }
    else if (row < 3072) { B = Bf; hi = fh; lo = fl; row -= 1024; }
    else                 { B = Bp; hi = ph; lo = pl; row -= 3072; }
    float2 v = *reinterpret_cast<const float2*>(B + row * 16 + j2);
    __nv_bfloat16 l0, l1;
    __nv_bfloat162 h = pack_split_hi(v.x, v.y, l0, l1);
    *reinterpret_cast<__nv_bfloat162*>(hi + row * 32 + j2) = h;
    *reinterpret_cast<__nv_bfloat162*>(lo + row * 32 + j2) = __nv_bfloat162(l0, l1);
    __nv_bfloat162 z2(__float2bfloat16(0.0f), __float2bfloat16(0.0f));
    *reinterpret_cast<__nv_bfloat162*>(hi + row * 32 + 16 + j2) = z2;
    *reinterpret_cast<__nv_bfloat162*>(lo + row * 32 + 16 + j2) = z2;
}

// ---------------------------------------------------------------------------
// merged LoRA intermediates for q and f
// ---------------------------------------------------------------------------
__global__ void __launch_bounds__(256)
lora_t_merged(const float* __restrict__ x,  const float* __restrict__ Aq,
              const float* __restrict__ ft, const float* __restrict__ Af,
              __nv_bfloat16* __restrict__ tqh, __nv_bfloat16* __restrict__ tql,
              __nv_bfloat16* __restrict__ tfh, __nv_bfloat16* __restrict__ tfl,
              float scale)
{
    __shared__ float xs[64][68];
    __shared__ float as_[16][65];

    const int tid = threadIdx.x;
    const float* X; const float* Am; __nv_bfloat16 *Th, *Tl; int bm;
    if (blockIdx.x < 128) { X = x;  Am = Aq; Th = tqh; Tl = tql; bm = blockIdx.x * 64; }
    else                  { X = ft; Am = Af; Th = tfh; Tl = tfl; bm = (blockIdx.x - 128) * 64; }

    const int r  = tid & 15;
    const int mg = tid >> 4;
    float a0 = 0.f, a1 = 0.f, a2 = 0.f, a3 = 0.f;

    for (int kt = 0; kt < 1024; kt += 64) {
#pragma unroll
        for (int i = tid; i < 1024; i += 256) {
            int row = i >> 4, c4 = i & 15;
            float4 v = *reinterpret_cast<const float4*>(
                &X[(long long)(bm + row) * 1024 + kt + c4 * 4]);
            *reinterpret_cast<float4*>(&xs[row][c4 * 4]) = v;
        }
#pragma unroll
        for (int i = tid; i < 1024; i += 256) {
            int row = i >> 6, kk = i & 63;
            as_[row][kk] = Am[row * 1024 + kt + kk];
        }
        __syncthreads();
#pragma unroll 16
        for (int kk = 0; kk < 64; kk++) {
            float a = as_[r][kk];
            a0 = fmaf(xs[mg * 4 + 0][kk], a, a0);
            a1 = fmaf(xs[mg * 4 + 1][kk], a, a1);
            a2 = fmaf(xs[mg * 4 + 2][kk], a, a2);
            a3 = fmaf(xs[mg * 4 + 3][kk], a, a3);
        }
        __syncthreads();
    }
    const __nv_bfloat16 z = __float2bfloat16(0.0f);
#pragma unroll
    for (int q = 0; q < 4; q++) {
        float v = (q == 0 ? a0 : q == 1 ? a1 : q == 2 ? a2 : a3) * scale;
        long long row = bm + mg * 4 + q;
        __nv_bfloat16 h = __float2bfloat16(v);
        __nv_bfloat16 l = __float2bfloat16(v - __bfloat162float(h));
        Th[row * 32 + r] = h;       Tl[row * 32 + r] = l;
        Th[row * 32 + 16 + r] = z;  Tl[row * 32 + 16 + r] = z;
    }
}

__global__ void __launch_bounds__(256)
lora_t_split(const __nv_bfloat16* __restrict__ Xhi, const __nv_bfloat16* __restrict__ Xlo,
             const float* __restrict__ Amat,
             __nv_bfloat16* __restrict__ Thi, __nv_bfloat16* __restrict__ Tlo,
             float scale)
{
    __shared__ float xs[64][68];
    __shared__ float as_[16][65];

    const int tid = threadIdx.x;
    const int bm  = blockIdx.x * 64;
    const int r   = tid & 15;
    const int mg  = tid >> 4;

    float a0 = 0.f, a1 = 0.f, a2 = 0.f, a3 = 0.f;

    for (int kt = 0; kt < 1024; kt += 64) {
#pragma unroll
        for (int i = tid; i < 1024; i += 256) {
            int row = i >> 4, c4 = i & 15;
            long long base = (long long)(bm + row) * 1024 + kt + c4 * 4;
            uint2 vh = *reinterpret_cast<const uint2*>(Xhi + base);
            uint2 vl = *reinterpret_cast<const uint2*>(Xlo + base);
            __nv_bfloat162 h0 = *reinterpret_cast<__nv_bfloat162*>(&vh.x);
            __nv_bfloat162 h1 = *reinterpret_cast<__nv_bfloat162*>(&vh.y);
            __nv_bfloat162 l0 = *reinterpret_cast<__nv_bfloat162*>(&vl.x);
            __nv_bfloat162 l1 = *reinterpret_cast<__nv_bfloat162*>(&vl.y);
            xs[row][c4*4+0] = __bfloat162float(h0.x) + __bfloat162float(l0.x);
            xs[row][c4*4+1] = __bfloat162float(h0.y) + __bfloat162float(l0.y);
            xs[row][c4*4+2] = __bfloat162float(h1.x) + __bfloat162float(l1.x);
            xs[row][c4*4+3] = __bfloat162float(h1.y) + __bfloat162float(l1.y);
        }
#pragma unroll
        for (int i = tid; i < 1024; i += 256) {
            int row = i >> 6, kk = i & 63;
            as_[row][kk] = Amat[row * 1024 + kt + kk];
        }
        __syncthreads();
#pragma unroll 16
        for (int kk = 0; kk < 64; kk++) {
            float a = as_[r][kk];
            a0 = fmaf(xs[mg * 4 + 0][kk], a, a0);
            a1 = fmaf(xs[mg * 4 + 1][kk], a, a1);
            a2 = fmaf(xs[mg * 4 + 2][kk], a, a2);
            a3 = fmaf(xs[mg * 4 + 3][kk], a, a3);
        }
        __syncthreads();
    }
    const __nv_bfloat16 z = __float2bfloat16(0.0f);
#pragma unroll
    for (int q = 0; q < 4; q++) {
        float v = (q == 0 ? a0 : q == 1 ? a1 : q == 2 ? a2 : a3) * scale;
        long long row = bm + mg * 4 + q;
        __nv_bfloat16 h = __float2bfloat16(v);
        __nv_bfloat16 l = __float2bfloat16(v - __bfloat162float(h));
        Thi[row * 32 + r] = h;       Tlo[row * 32 + r] = l;
        Thi[row * 32 + 16 + r] = z;  Tlo[row * 32 + 16 + r] = z;
    }
}

// ---------------------------------------------------------------------------
// split-bf16 mma.sync GEMM, 3-stage pipeline, warp tile 32x64 (R6 config)
// ---------------------------------------------------------------------------
#define MG_STAGE 32768
#define MG_SMEM  (3 * MG_STAGE)

template<bool SPLIT_OUT>
__global__ void __launch_bounds__(256, 2)
mma_gemm(const __nv_bfloat16* __restrict__ Ahi, const __nv_bfloat16* __restrict__ Alo,
         const __nv_bfloat16* __restrict__ Bhi, const __nv_bfloat16* __restrict__ Blo,
         const __nv_bfloat16* __restrict__ LThi, const __nv_bfloat16* __restrict__ LTlo,
         const __nv_bfloat16* __restrict__ LBhi, const __nv_bfloat16* __restrict__ LBlo,
         float* __restrict__ C, __nv_bfloat16* __restrict__ Chi,
         __nv_bfloat16* __restrict__ Clo,
         int K, int N, const float* __restrict__ bias)
{
    extern __shared__ char smem[];
    const uint32_t sb = smem_u32(smem);
    const int tid  = threadIdx.x;
    const int lane = tid & 31;
    const int warp = tid >> 5;
    const int wm   = warp >> 1;
    const int wn   = warp & 1;
    const int bm = blockIdx.y * 128;
    const int bn = blockIdx.x * 128;

    const int KCH = K >> 5;
    const int NC  = KCH + 1;

    float acc[2][8][4];
#pragma unroll
    for (int m = 0; m < 2; m++)
#pragma unroll
        for (int n = 0; n < 8; n++)
#pragma unroll
            for (int j = 0; j < 4; j++) acc[m][n][j] = 0.0f;

    auto load_chunk = [&](int ch, int st) {
        const bool lora = (ch == KCH);
        const int kt = ch << 5;
#pragma unroll
        for (int i = tid; i < 2048; i += 256) {
            int tile = i >> 9;
            int idx  = i & 511;
            int row  = idx >> 2;
            int c4   = idx & 3;
            const __nv_bfloat16* g;
            long long off;
            if (!lora) {
                g = (tile == 0) ? Ahi : (tile == 1) ? Alo : (tile == 2) ? Bhi : Blo;
                int r0 = (tile < 2) ? bm : bn;
                off = (long long)(r0 + row) * K + kt + c4 * 8;
            } else {
                g = (tile == 0) ? LThi : (tile == 1) ? LTlo : (tile == 2) ? LBhi : LBlo;
                int r0 = (tile < 2) ? bm : bn;
                off = (long long)(r0 + row) * 32 + c4 * 8;
            }
            uint32_t dst = sb + st * MG_STAGE + tile * 8192 + row * 64
                         + ((c4 ^ ((row >> 1) & 3)) << 4);
            cp16(dst, g + off);
        }
        cp_commit();
    };

    load_chunk(0, 0);
    load_chunk(1, 1);

    for (int ch = 0; ch < NC; ch++) {
        const int st = ch % 3;
        if (ch + 2 < NC) {
            load_chunk(ch + 2, (ch + 2) % 3);
            asm volatile("cp.async.wait_group 2;" ::: "memory");
        } else if (ch + 1 < NC) {
            asm volatile("cp.async.wait_group 1;" ::: "memory");
        } else {
            asm volatile("cp.async.wait_group 0;" ::: "memory");
        }
        __syncthreads();

        const uint32_t stb = sb + st * MG_STAGE;
#pragma unroll
        for (int kk = 0; kk < 2; kk++) {
            uint32_t ah[2][4], al[2][4];
#pragma unroll
            for (int mf = 0; mf < 2; mf++) {
                int row = wm * 32 + mf * 16 + (lane & 15);
                int c4  = kk * 2 + (lane >> 4);
                uint32_t sw = (uint32_t)((c4 ^ ((row >> 1) & 3)) << 4);
                uint32_t ad = stb + row * 64 + sw;
                ldm_x4(ah[mf][0], ah[mf][1], ah[mf][2], ah[mf][3], ad);
                ldm_x4(al[mf][0], al[mf][1], al[mf][2], al[mf][3], ad + 8192);
            }
            uint32_t bh[8][2], bl[8][2];
#pragma unroll
            for (int p = 0; p < 4; p++) {
                int row = wn * 64 + p * 16 + (lane & 15);
                int c4  = kk * 2 + (lane >> 4);
                uint32_t sw = (uint32_t)((c4 ^ ((row >> 1) & 3)) << 4);
                uint32_t ad = stb + 16384 + row * 64 + sw;
                uint32_t r0, r1, r2, r3;
                ldm_x4(r0, r1, r2, r3, ad);
                bh[2*p][0] = r0; bh[2*p][1] = r2;
                bh[2*p+1][0] = r1; bh[2*p+1][1] = r3;
                ldm_x4(r0, r1, r2, r3, ad + 8192);
                bl[2*p][0] = r0; bl[2*p][1] = r2;
                bl[2*p+1][0] = r1; bl[2*p+1][1] = r3;
            }
#pragma unroll
            for (int mf = 0; mf < 2; mf++)
#pragma unroll
                for (int n = 0; n < 8; n++) {
                    mma_bf16(acc[mf][n], ah[mf], bh[n]);
                    mma_bf16(acc[mf][n], ah[mf], bl[n]);
                    mma_bf16(acc[mf][n], al[mf], bh[n]);
                }
        }
        __syncthreads();
    }

#pragma unroll
    for (int mf = 0; mf < 2; mf++) {
        int r1 = bm + wm * 32 + mf * 16 + (lane >> 2);
#pragma unroll
        for (int n = 0; n < 8; n++) {
            int col = bn + wn * 64 + n * 8 + (lane & 3) * 2;
            float b0 = bias[col], b1 = bias[col + 1];
            float v00 = acc[mf][n][0] + b0, v01 = acc[mf][n][1] + b1;
            float v10 = acc[mf][n][2] + b0, v11 = acc[mf][n][3] + b1;
            if (SPLIT_OUT) {
                __nv_bfloat16 l0, l1;
                __nv_bfloat162 h = pack_split_hi(v00, v01, l0, l1);
                *reinterpret_cast<__nv_bfloat162*>(&Chi[(long long)r1 * N + col]) = h;
                *reinterpret_cast<__nv_bfloat162*>(&Clo[(long long)r1 * N + col]) =
                    __nv_bfloat162(l0, l1);
                h = pack_split_hi(v10, v11, l0, l1);
                *reinterpret_cast<__nv_bfloat162*>(&Chi[(long long)(r1 + 8) * N + col]) = h;
                *reinterpret_cast<__nv_bfloat162*>(&Clo[(long long)(r1 + 8) * N + col]) =
                    __nv_bfloat162(l0, l1);
            } else {
                *reinterpret_cast<float2*>(&C[(long long)r1 * N + col]) =
                    make_float2(v00, v01);
                *reinterpret_cast<float2*>(&C[(long long)(r1 + 8) * N + col]) =
                    make_float2(v10, v11);
            }
        }
    }
}

// ---------------------------------------------------------------------------
// Persistent fused attention (256 threads) + Q double-buffer prefetch
// smem layout:
//  Khi@0 Klo@32K Vhi@64K Vlo@96K (32 KB each)
//  Q0hi@131072 Q0lo@139264 (8 KB each)
//  Phi@147456 Plo@180224 (32 KB each)
//  redmax@212992 (1K) redsum@214016 (1K)
//  Q1hi@215040 Q1lo@223232 (8 KB each)  -> total 231424 B
// ---------------------------------------------------------------------------
#define FA_KH   0
#define FA_KL   32768
#define FA_VH   65536
#define FA_VL   98304
#define FA_Q0   131072
#define FA_PH   147456
#define FA_PL   180224
#define FA_REDM 212992
#define FA_REDS 214016
#define FA_Q1   215040
#define FA_SMEM 231424

__global__ void __launch_bounds__(256)
fa_kernel(const __nv_bfloat16* __restrict__ Qh, const __nv_bfloat16* __restrict__ Ql,
          const __nv_bfloat16* __restrict__ KVh, const __nv_bfloat16* __restrict__ KVl,
          __nv_bfloat16* __restrict__ Yh, __nv_bfloat16* __restrict__ Yl)
{
    extern __shared__ char smem[];
    const uint32_t sb = smem_u32(smem);
    const int tid  = threadIdx.x;
    const int lane = tid & 31;
    const int warp = tid >> 5;
    const int bh = blockIdx.x;
    const int b = bh >> 4, h = bh & 15;

    const int rq = lane >> 2, cq = lane & 3;
    const int wm = warp >> 2;
    const int wn = warp & 3;

    float* red_max = reinterpret_cast<float*>(smem + FA_REDM);
    float* red_sum = reinterpret_cast<float*>(smem + FA_REDS);

    const long long qstride = 1024;
    const long long qbase0  = ((long long)(b * 1024)) * 1024 + h * 64;

    auto load_q = [&](int tt, uint32_t qbuf) {
        const long long qbase = qbase0 + (long long)(tt * 64) * qstride;
#pragma unroll
        for (int i = tid; i < 512; i += 256) {
            int row = i >> 3, c = i & 7;
            uint32_t sw = (uint32_t)((c ^ (row & 7)) << 4);
            cp16(sb + qbuf + row * 128 + sw,        Qh + qbase + (long long)row * qstride + c * 8);
            cp16(sb + qbuf + 8192 + row * 128 + sw, Ql + qbase + (long long)row * qstride + c * 8);
        }
        cp_commit();
    };

    // ---- load K, V once + first Q tile ----
    {
        const long long kbase = ((long long)(b * 256)) * 2048 + h * 64;
#pragma unroll
        for (int i = tid; i < 2048; i += 256) {
            int row = i >> 3, c = i & 7;
            uint32_t sw = (uint32_t)((c ^ (row & 7)) << 4);
            long long go = (long long)row * 2048 + c * 8;
            cp16(sb + FA_KH + row * 128 + sw, KVh + kbase + go);
            cp16(sb + FA_KL + row * 128 + sw, KVl + kbase + go);
            cp16(sb + FA_VH + row * 128 + sw, KVh + kbase + 1024 + go);
            cp16(sb + FA_VL + row * 128 + sw, KVl + kbase + 1024 + go);
        }
        cp_commit();
        load_q(0, FA_Q0);
        asm volatile("cp.async.wait_group 0;" ::: "memory");
        __syncthreads();
    }

    for (int tt = 0; tt < 16; tt++) {
        const int t0 = tt * 64;
        const bool need_mask = (t0 < Slen);
        const int tmax = t0 + 63;
        const uint32_t qb = (tt & 1) ? FA_Q1 : FA_Q0;

        if (tt > 0) {
            asm volatile("cp.async.wait_group 0;" ::: "memory");
            __syncthreads();
        }

        // ---- phase 1: S = Q K^T ----
        float acc[2][8][4];
#pragma unroll
        for (int m = 0; m < 2; m++)
#pragma unroll
            for (int n = 0; n < 8; n++)
#pragma unroll
                for (int j = 0; j < 4; j++) acc[m][n][j] = 0.0f;

#pragma unroll
        for (int ks = 0; ks < 4; ks++) {
            uint32_t ah[2][4], al[2][4];
#pragma unroll
            for (int mf = 0; mf < 2; mf++) {
                int row = wm * 32 + mf * 16 + (lane & 15);
                int ch  = ks * 2 + (lane >> 4);
                uint32_t ad = sb + qb + row * 128 + (uint32_t)((ch ^ (row & 7)) << 4);
                ldm_x4(ah[mf][0], ah[mf][1], ah[mf][2], ah[mf][3], ad);
                ldm_x4(al[mf][0], al[mf][1], al[mf][2], al[mf][3], ad + 8192);
            }
            uint32_t bh_[8][2], bl_[8][2];
#pragma unroll
            for (int p = 0; p < 4; p++) {
                if (need_mask && (wn * 64 + p * 16) > tmax) continue;
                int row = wn * 64 + p * 16 + (lane & 15);
                int ch  = ks * 2 + (lane >> 4);
                uint32_t ad = sb + FA_KH + row * 128 + (uint32_t)((ch ^ (row & 7)) << 4);
                uint32_t r0, r1, r2, r3;
                ldm_x4(r0, r1, r2, r3, ad);
                bh_[2*p][0] = r0; bh_[2*p][1] = r2;
                bh_[2*p+1][0] = r1; bh_[2*p+1][1] = r3;
                ldm_x4(r0, r1, r2, r3, ad + 32768);
                bl_[2*p][0] = r0; bl_[2*p][1] = r2;
                bl_[2*p+1][0] = r1; bl_[2*p+1][1] = r3;
            }
#pragma unroll
            for (int mf = 0; mf < 2; mf++)
#pragma unroll
                for (int n = 0; n < 8; n++) {
                    if (need_mask && (wn * 64 + n * 8) > tmax) continue;
                    mma_bf16(acc[mf][n], ah[mf], bh_[n]);
                    mma_bf16(acc[mf][n], ah[mf], bl_[n]);
                    mma_bf16(acc[mf][n], al[mf], bh_[n]);
                }
        }

        // ---- prefetch next Q into the other buffer ----
        if (tt + 1 < 16) load_q(tt + 1, (tt & 1) ? FA_Q0 : FA_Q1);

        // ---- softmax ----
#pragma unroll
        for (int mf = 0; mf < 2; mf++)
#pragma unroll
            for (int sub = 0; sub < 2; sub++) {
                int rl = wm * 32 + mf * 16 + sub * 8 + rq;
                int trow = t0 + rl;
                float m = -1e30f;
#pragma unroll
                for (int nf = 0; nf < 8; nf++) {
                    int col = wn * 64 + nf * 8 + cq * 2;
                    float v0 = acc[mf][nf][sub*2]     * 0.125f;
                    float v1 = acc[mf][nf][sub*2 + 1] * 0.125f;
                    if (need_mask) {
                        if (col     > trow) v0 = -1e30f;
                        if (col + 1 > trow) v1 = -1e30f;
                    }
                    acc[mf][nf][sub*2]     = v0;
                    acc[mf][nf][sub*2 + 1] = v1;
                    m = fmaxf(m, fmaxf(v0, v1));
                }
                m = fmaxf(m, __shfl_xor_sync(0xffffffffu, m, 1));
                m = fmaxf(m, __shfl_xor_sync(0xffffffffu, m, 2));
                if (cq == 0) red_max[wn * 64 + rl] = m;
            }
        __syncthreads();

#pragma unroll
        for (int mf = 0; mf < 2; mf++)
#pragma unroll
            for (int sub = 0; sub < 2; sub++) {
                int rl = wm * 32 + mf * 16 + sub * 8 + rq;
                float M = fmaxf(fmaxf(red_max[rl], red_max[64 + rl]),
                                fmaxf(red_max[128 + rl], red_max[192 + rl]));
                float s = 0.0f;
#pragma unroll
                for (int nf = 0; nf < 8; nf++) {
                    float e0 = __expf(acc[mf][nf][sub*2]     - M);
                    float e1 = __expf(acc[mf][nf][sub*2 + 1] - M);
                    acc[mf][nf][sub*2]     = e0;
                    acc[mf][nf][sub*2 + 1] = e1;
                    s += e0 + e1;
                }
                s += __shfl_xor_sync(0xffffffffu, s, 1);
                s += __shfl_xor_sync(0xffffffffu, s, 2);
                if (cq == 0) red_sum[wn * 64 + rl] = s;
            }
        __syncthreads();

        // ---- store P split bf16 ----
#pragma unroll
        for (int mf = 0; mf < 2; mf++)
#pragma unroll
            for (int sub = 0; sub < 2; sub++) {
                int rl = wm * 32 + mf * 16 + sub * 8 + rq;
#pragma unroll
                for (int nf = 0; nf < 8; nf++) {
                    int col = wn * 64 + nf * 8 + cq * 2;
                    __nv_bfloat16 l0, l1;
                    __nv_bfloat162 hh = pack_split_hi(acc[mf][nf][sub*2],
                                                      acc[mf][nf][sub*2 + 1], l0, l1);
                    int chnk = col >> 3;
                    uint32_t off = (uint32_t)(rl * 512 + ((chnk ^ (rl & 7)) << 4) + (col & 7) * 2);
                    *reinterpret_cast<__nv_bfloat162*>(smem + FA_PH + off) = hh;
                    *reinterpret_cast<__nv_bfloat162*>(smem + FA_PL + off) =
                        __nv_bfloat162(l0, l1);
                }
            }
        __syncthreads();

        // ---- phase 2: Y = P V ----
        const int nks = need_mask ? ((tmax >> 4) + 1) : 16;
        float acc2[2][2][4];
#pragma unroll
        for (int m = 0; m < 2; m++)
#pragma unroll
            for (int n = 0; n < 2; n++)
#pragma unroll
                for (int j = 0; j < 4; j++) acc2[m][n][j] = 0.0f;

        for (int ks = 0; ks < nks; ks++) {
            uint32_t ph[2][4], pl[2][4];
#pragma unroll
            for (int mf = 0; mf < 2; mf++) {
                int row = wm * 32 + mf * 16 + (lane & 15);
                int ch  = ks * 2 + (lane >> 4);
                uint32_t ad = sb + FA_PH + row * 512 + (uint32_t)((ch ^ (row & 7)) << 4);
                ldm_x4(ph[mf][0], ph[mf][1], ph[mf][2], ph[mf][3], ad);
                ldm_x4(pl[mf][0], pl[mf][1], pl[mf][2], pl[mf][3], ad + 32768);
            }
            uint32_t vh_[2][2], vl_[2][2];
            {
                int g = lane >> 3;
                int srow = ks * 16 + (g & 1) * 8 + (lane & 7);
                int dch  = wn * 2 + (g >> 1);
                uint32_t ad = sb + FA_VH + srow * 128 + (uint32_t)((dch ^ (srow & 7)) << 4);
                uint32_t r0, r1, r2, r3;
                ldm_x4t(r0, r1, r2, r3, ad);
                vh_[0][0] = r0; vh_[0][1] = r1; vh_[1][0] = r2; vh_[1][1] = r3;
                ldm_x4t(r0, r1, r2, r3, ad + 32768);
                vl_[0][0] = r0; vl_[0][1] = r1; vl_[1][0] = r2; vl_[1][1] = r3;
            }
#pragma unroll
            for (int mf = 0; mf < 2; mf++)
#pragma unroll
                for (int nf = 0; nf < 2; nf++) {
                    mma_bf16(acc2[mf][nf], ph[mf], vh_[nf]);
                    mma_bf16(acc2[mf][nf], ph[mf], vl_[nf]);
                    mma_bf16(acc2[mf][nf], pl[mf], vh_[nf]);
                }
        }

        // ---- epilogue ----
#pragma unroll
        for (int mf = 0; mf < 2; mf++)
#pragma unroll
            for (int sub = 0; sub < 2; sub++) {
                int rl = wm * 32 + mf * 16 + sub * 8 + rq;
                float inv = 1.0f / (red_sum[rl] + red_sum[64 + rl] +
                                    red_sum[128 + rl] + red_sum[192 + rl]);
                long long yo = ((long long)(b * 1024 + t0 + rl)) * 1024 + h * 64;
#pragma unroll
                for (int nf = 0; nf < 2; nf++) {
                    int col = wn * 16 + nf * 8 + cq * 2;
                    float v0 = acc2[mf][nf][sub*2]     * inv;
                    float v1 = acc2[mf][nf][sub*2 + 1] * inv;
                    __nv_bfloat16 l0, l1;
                    __nv_bfloat162 hh = pack_split_hi(v0, v1, l0, l1);
                    *reinterpret_cast<__nv_bfloat162*>(&Yh[yo + col]) = hh;
                    *reinterpret_cast<__nv_bfloat162*>(&Yl[yo + col]) = __nv_bfloat162(l0, l1);
                }
            }
        __syncthreads();
    }
}

// ---------------------------------------------------------------------------
// Launch
// ---------------------------------------------------------------------------
extern "C" void kernel_launch(void* const* d_in, const int* in_sizes, int n_in,
                              void* d_out, int out_size)
{
    const float* x  = (const float*)d_in[0];
    const float* ft = (const float*)d_in[1];
    const float* Wq = (const float*)d_in[2];
    const float* bq = (const float*)d_in[3];
    const float* Aq = (const float*)d_in[4];
    const float* Bq = (const float*)d_in[5];
    const float* Wf = (const float*)d_in[6];
    const float* bfv= (const float*)d_in[7];
    const float* Af = (const float*)d_in[8];
    const float* Bf = (const float*)d_in[9];
    const float* Wp = (const float*)d_in[10];
    const float* bp = (const float*)d_in[11];
    const float* Ap = (const float*)d_in[12];
    const float* Bp = (const float*)d_in[13];
    float* out = (float*)d_out;

    __nv_bfloat16 *xhi, *xlo, *fhi, *flo, *yhi, *ylo;
    __nv_bfloat16 *wqhi, *wqlo, *wfhi, *wflo, *wphi, *wplo;
    __nv_bfloat16 *qh, *ql, *kvh, *kvl;
    __nv_bfloat16 *tqh, *tql, *tfh, *tfl, *tph, *tpl;
    __nv_bfloat16 *bqh, *bql, *bfh, *bfl, *bph, *bpl;
    cudaGetSymbolAddress((void**)&xhi, g_xhi);  cudaGetSymbolAddress((void**)&xlo, g_xlo);
    cudaGetSymbolAddress((void**)&fhi, g_fhi);  cudaGetSymbolAddress((void**)&flo, g_flo);
    cudaGetSymbolAddress((void**)&yhi, g_yhi);  cudaGetSymbolAddress((void**)&ylo, g_ylo);
    cudaGetSymbolAddress((void**)&wqhi, g_wqhi); cudaGetSymbolAddress((void**)&wqlo, g_wqlo);
    cudaGetSymbolAddress((void**)&wfhi, g_wfhi); cudaGetSymbolAddress((void**)&wflo, g_wflo);
    cudaGetSymbolAddress((void**)&wphi, g_wphi); cudaGetSymbolAddress((void**)&wplo, g_wplo);
    cudaGetSymbolAddress((void**)&qh, g_qh);    cudaGetSymbolAddress((void**)&ql, g_ql);
    cudaGetSymbolAddress((void**)&kvh, g_kvh);  cudaGetSymbolAddress((void**)&kvl, g_kvl);
    cudaGetSymbolAddress((void**)&tqh, g_tqh);  cudaGetSymbolAddress((void**)&tql, g_tql);
    cudaGetSymbolAddress((void**)&tfh, g_tfh);  cudaGetSymbolAddress((void**)&tfl, g_tfl);
    cudaGetSymbolAddress((void**)&tph, g_tph);  cudaGetSymbolAddress((void**)&tpl, g_tpl);
    cudaGetSymbolAddress((void**)&bqh, g_bqh);  cudaGetSymbolAddress((void**)&bql, g_bql);
    cudaGetSymbolAddress((void**)&bfh, g_bfh);  cudaGetSymbolAddress((void**)&bfl, g_bfl);
    cudaGetSymbolAddress((void**)&bph, g_bph);  cudaGetSymbolAddress((void**)&bpl, g_bpl);

    cudaFuncSetAttribute(mma_gemm<false>, cudaFuncAttributeMaxDynamicSharedMemorySize, MG_SMEM);
    cudaFuncSetAttribute(mma_gemm<true>,  cudaFuncAttributeMaxDynamicSharedMemorySize, MG_SMEM);
    cudaFuncSetAttribute(fa_kernel, cudaFuncAttributeMaxDynamicSharedMemorySize, FA_SMEM);

    const float SC = 1.0f / 16.0f;

    split_multi<<<(SEG4 + 255)/256, 256>>>(
        (const float4*)x, (const float4*)Wq, (const float4*)ft,
        (const float4*)Wf, (const float4*)Wp,
        (__nv_bfloat162*)xhi,  (__nv_bfloat162*)xlo,
        (__nv_bfloat162*)wqhi, (__nv_bfloat162*)wqlo,
        (__nv_bfloat162*)fhi,  (__nv_bfloat162*)flo,
        (__nv_bfloat162*)wfhi, (__nv_bfloat162*)wflo,
        (__nv_bfloat162*)wphi, (__nv_bfloat162*)wplo);

    lora_t_merged<<<160, 256>>>(x, Aq, ft, Af, tqh, tql, tfh, tfl, SC);
    splitpad_multi<<<128, 256>>>(Bq, Bf, Bp, bqh, bql, bfh, bfl, bph, bpl);

    // Q projection -> split bf16
    mma_gemm<true><<<dim3(8, 64), 256, MG_SMEM>>>(xhi, xlo, wqhi, wqlo,
        tqh, tql, bqh, bql, nullptr, qh, ql, 1024, 1024, bq);

    // KV projection -> split bf16
    mma_gemm<true><<<dim3(16, 16), 256, MG_SMEM>>>(fhi, flo, wfhi, wflo,
        tfh, tfl, bfh, bfl, nullptr, kvh, kvl, 1024, 2048, bfv);

    // persistent fused attention -> split bf16 Y
    fa_kernel<<<128, 256, FA_SMEM>>>(qh, ql, kvh, kvl, yhi, ylo);

    // LoRA for P from split Y
    lora_t_split<<<128, 256>>>(yhi, ylo, Ap, tph, tpl, SC);

    // out = y @ Wp^T + bp + lora  (fp32 out)
    mma_gemm<false><<<dim3(8, 64), 256, MG_SMEM>>>(yhi, ylo, wphi, wplo,
        tph, tpl, bph, bpl, out, nullptr, nullptr, 1024, 1024, bp);
}

// round 17
// speedup vs baseline: 2.0753x; 1.3392x over previous
#include <cuda_runtime.h>
#include <cuda_fp16.h>
#include <math.h>
#include <stdint.h>

// ---------------------------------------------------------------------------
// CrossAttention with LoRA — round 17: fp16 2-term projections
// (activation rounded once to fp16; weights split hi/lo; attention 3-term fp16)
// B=8, T=1024, S=256, C=1024, H=16, D=64, R=16, SCALING=1/16
// ---------------------------------------------------------------------------

#define Bsz   8
#define Tlen  1024
#define Slen  256
#define Cdim  1024

// activations: single fp16
__device__ __align__(16) __half g_xh[Bsz*Tlen*Cdim];
__device__ __align__(16) __half g_fh[Bsz*Slen*Cdim];
__device__ __align__(16) __half g_yh[Bsz*Tlen*Cdim];
// weights: fp16 hi/lo pairs
__device__ __align__(16) __half g_wqh[Cdim*Cdim],   g_wql[Cdim*Cdim];
__device__ __align__(16) __half g_wfh[2*Cdim*Cdim], g_wfl[2*Cdim*Cdim];
__device__ __align__(16) __half g_wph[Cdim*Cdim],   g_wpl[Cdim*Cdim];
// projection outputs: fp16 hi/lo pairs (for 3-term attention)
__device__ __align__(16) __half g_qh[Bsz*Tlen*Cdim],    g_ql[Bsz*Tlen*Cdim];
__device__ __align__(16) __half g_kvh[Bsz*Slen*2*Cdim], g_kvl[Bsz*Slen*2*Cdim];
// LoRA: lt single fp16 (pre-scaled, padded to 32), lb pairs (padded to 32)
__device__ __align__(16) __half g_tq[Bsz*Tlen*32];
__device__ __align__(16) __half g_tf[Bsz*Slen*32];
__device__ __align__(16) __half g_tp[Bsz*Tlen*32];
__device__ __align__(16) __half g_bqh[Cdim*32],   g_bql[Cdim*32];
__device__ __align__(16) __half g_bfh[2*Cdim*32], g_bfl[2*Cdim*32];
__device__ __align__(16) __half g_bph[Cdim*32],   g_bpl[Cdim*32];

// ---------------------------------------------------------------------------
__device__ __forceinline__ uint32_t smem_u32(const void* p) {
    uint32_t a;
    asm("{ .reg .u64 t; cvta.to.shared.u64 t, %1; cvt.u32.u64 %0, t; }" : "=r"(a) : "l"(p));
    return a;
}
__device__ __forceinline__ void cp16(uint32_t dst, const void* src) {
    asm volatile("cp.async.cg.shared.global [%0], [%1], 16;" :: "r"(dst), "l"(src));
}
__device__ __forceinline__ void cp_commit() {
    asm volatile("cp.async.commit_group;" ::: "memory");
}
__device__ __forceinline__ void ldm_x4(uint32_t& r0, uint32_t& r1, uint32_t& r2, uint32_t& r3,
                                       uint32_t addr) {
    asm volatile("ldmatrix.sync.aligned.m8n8.x4.shared.b16 {%0,%1,%2,%3}, [%4];"
                 : "=r"(r0), "=r"(r1), "=r"(r2), "=r"(r3) : "r"(addr));
}
__device__ __forceinline__ void ldm_x4t(uint32_t& r0, uint32_t& r1, uint32_t& r2, uint32_t& r3,
                                        uint32_t addr) {
    asm volatile("ldmatrix.sync.aligned.m8n8.x4.trans.shared.b16 {%0,%1,%2,%3}, [%4];"
                 : "=r"(r0), "=r"(r1), "=r"(r2), "=r"(r3) : "r"(addr));
}
__device__ __forceinline__ void mma_f16(float* c, const uint32_t* a, const uint32_t* b) {
    asm("mma.sync.aligned.m16n8k16.row.col.f32.f16.f16.f32 "
        "{%0,%1,%2,%3}, {%4,%5,%6,%7}, {%8,%9}, {%0,%1,%2,%3};"
        : "+f"(c[0]), "+f"(c[1]), "+f"(c[2]), "+f"(c[3])
        : "r"(a[0]), "r"(a[1]), "r"(a[2]), "r"(a[3]), "r"(b[0]), "r"(b[1]));
}
__device__ __forceinline__ __half2 pack_split_h(float v0, float v1, __half& l0, __half& l1) {
    __half h0 = __float2half_rn(v0);
    __half h1 = __float2half_rn(v1);
    l0 = __float2half_rn(v0 - __half2float(h0));
    l1 = __float2half_rn(v1 - __half2float(h1));
    return __halves2half2(h0, h1);
}

// ---------------------------------------------------------------------------
// activation rounding: fp32 -> fp16 (single), x then ft
// ---------------------------------------------------------------------------
#define AX4 (Bsz*Tlen*Cdim/4)           // 2097152
#define AF4 (AX4 + Bsz*Slen*Cdim/4)     // + 524288

__global__ void __launch_bounds__(256)
split_act(const float4* __restrict__ x, const float4* __restrict__ ft,
          __half2* __restrict__ xh, __half2* __restrict__ fh)
{
    int gi = blockIdx.x * 256 + threadIdx.x;
    if (gi >= AF4) return;
    const float4* in; __half2* o; int i;
    if (gi < AX4) { in = x;  o = xh; i = gi; }
    else          { in = ft; o = fh; i = gi - AX4; }
    float4 v = in[i];
    o[2*i]   = __floats2half2_rn(v.x, v.y);
    o[2*i+1] = __floats2half2_rn(v.z, v.w);
}

// weight splitting: fp32 -> (hi, lo) fp16 pairs; Wq, Wf, Wp
#define WQ4 (Cdim*Cdim/4)
#define WF4 (WQ4 + 2*Cdim*Cdim/4)
#define WP4 (WF4 + Cdim*Cdim/4)

__global__ void __launch_bounds__(256)
split_w(const float4* __restrict__ Wq, const float4* __restrict__ Wf,
        const float4* __restrict__ Wp,
        __half2* __restrict__ wqh, __half2* __restrict__ wql,
        __half2* __restrict__ wfh, __half2* __restrict__ wfl,
        __half2* __restrict__ wph, __half2* __restrict__ wpl)
{
    int gi = blockIdx.x * 256 + threadIdx.x;
    if (gi >= WP4) return;
    const float4* in; __half2* hi; __half2* lo; int i;
    if (gi < WQ4)      { in = Wq; hi = wqh; lo = wql; i = gi; }
    else if (gi < WF4) { in = Wf; hi = wfh; lo = wfl; i = gi - WQ4; }
    else               { in = Wp; hi = wph; lo = wpl; i = gi - WF4; }
    float4 v = in[i];
    __half l0, l1, l2, l3;
    __half2 h01 = pack_split_h(v.x, v.y, l0, l1);
    __half2 h23 = pack_split_h(v.z, v.w, l2, l3);
    hi[2*i]   = h01;
    hi[2*i+1] = h23;
    lo[2*i]   = __halves2half2(l0, l1);
    lo[2*i+1] = __halves2half2(l2, l3);
}

// splitpad for LoRA B matrices: rows x16 fp32 -> rows x32 fp16 pairs
__global__ void __launch_bounds__(256)
splitpad_multi(const float* __restrict__ Bq, const float* __restrict__ Bf,
               const float* __restrict__ Bp,
               __half* __restrict__ qh, __half* __restrict__ ql,
               __half* __restrict__ fh, __half* __restrict__ fl,
               __half* __restrict__ ph, __half* __restrict__ pl)
{
    int g = blockIdx.x * 256 + threadIdx.x;
    if (g >= 32768) return;
    int row = g >> 3;
    int j2  = (g & 7) * 2;
    const float* B; __half* hi; __half* lo;
    if (row < 1024)      { B = Bq; hi = qh; lo = ql; }
    else if (row < 3072) { B = Bf; hi = fh; lo = fl; row -= 1024; }
    else                 { B = Bp; hi = ph; lo = pl; row -= 3072; }
    float2 v = *reinterpret_cast<const float2*>(B + row * 16 + j2);
    __half l0, l1;
    __half2 h = pack_split_h(v.x, v.y, l0, l1);
    *reinterpret_cast<__half2*>(hi + row * 32 + j2) = h;
    *reinterpret_cast<__half2*>(lo + row * 32 + j2) = __halves2half2(l0, l1);
    __half2 z2 = __floats2half2_rn(0.0f, 0.0f);
    *reinterpret_cast<__half2*>(hi + row * 32 + 16 + j2) = z2;
    *reinterpret_cast<__half2*>(lo + row * 32 + 16 + j2) = z2;
}

// ---------------------------------------------------------------------------
// merged LoRA intermediates (single fp16 output, pre-scaled, padded to 32)
// ---------------------------------------------------------------------------
__global__ void __launch_bounds__(256)
lora_t_merged(const float* __restrict__ x,  const float* __restrict__ Aq,
              const float* __restrict__ ft, const float* __restrict__ Af,
              __half* __restrict__ tq, __half* __restrict__ tf, float scale)
{
    __shared__ float xs[64][68];
    __shared__ float as_[16][65];

    const int tid = threadIdx.x;
    const float* X; const float* Am; __half* T; int bm;
    if (blockIdx.x < 128) { X = x;  Am = Aq; T = tq; bm = blockIdx.x * 64; }
    else                  { X = ft; Am = Af; T = tf; bm = (blockIdx.x - 128) * 64; }

    const int r  = tid & 15;
    const int mg = tid >> 4;
    float a0 = 0.f, a1 = 0.f, a2 = 0.f, a3 = 0.f;

    for (int kt = 0; kt < 1024; kt += 64) {
#pragma unroll
        for (int i = tid; i < 1024; i += 256) {
            int row = i >> 4, c4 = i & 15;
            float4 v = *reinterpret_cast<const float4*>(
                &X[(long long)(bm + row) * 1024 + kt + c4 * 4]);
            *reinterpret_cast<float4*>(&xs[row][c4 * 4]) = v;
        }
#pragma unroll
        for (int i = tid; i < 1024; i += 256) {
            int row = i >> 6, kk = i & 63;
            as_[row][kk] = Am[row * 1024 + kt + kk];
        }
        __syncthreads();
#pragma unroll 16
        for (int kk = 0; kk < 64; kk++) {
            float a = as_[r][kk];
            a0 = fmaf(xs[mg * 4 + 0][kk], a, a0);
            a1 = fmaf(xs[mg * 4 + 1][kk], a, a1);
            a2 = fmaf(xs[mg * 4 + 2][kk], a, a2);
            a3 = fmaf(xs[mg * 4 + 3][kk], a, a3);
        }
        __syncthreads();
    }
    const __half z = __float2half_rn(0.0f);
#pragma unroll
    for (int q = 0; q < 4; q++) {
        float v = (q == 0 ? a0 : q == 1 ? a1 : q == 2 ? a2 : a3) * scale;
        long long row = bm + mg * 4 + q;
        T[row * 32 + r] = __float2half_rn(v);
        T[row * 32 + 16 + r] = z;
    }
}

// LoRA intermediate from single-fp16 Y
__global__ void __launch_bounds__(256)
lora_t_half(const __half* __restrict__ Yh, const float* __restrict__ Amat,
            __half* __restrict__ T, float scale)
{
    __shared__ float xs[64][68];
    __shared__ float as_[16][65];

    const int tid = threadIdx.x;
    const int bm  = blockIdx.x * 64;
    const int r   = tid & 15;
    const int mg  = tid >> 4;

    float a0 = 0.f, a1 = 0.f, a2 = 0.f, a3 = 0.f;

    for (int kt = 0; kt < 1024; kt += 64) {
#pragma unroll
        for (int i = tid; i < 1024; i += 256) {
            int row = i >> 4, c4 = i & 15;
            long long base = (long long)(bm + row) * 1024 + kt + c4 * 4;
            uint2 vh = *reinterpret_cast<const uint2*>(Yh + base);
            __half2 h0 = *reinterpret_cast<__half2*>(&vh.x);
            __half2 h1 = *reinterpret_cast<__half2*>(&vh.y);
            xs[row][c4*4+0] = __half2float(h0.x);
            xs[row][c4*4+1] = __half2float(h0.y);
            xs[row][c4*4+2] = __half2float(h1.x);
            xs[row][c4*4+3] = __half2float(h1.y);
        }
#pragma unroll
        for (int i = tid; i < 1024; i += 256) {
            int row = i >> 6, kk = i & 63;
            as_[row][kk] = Amat[row * 1024 + kt + kk];
        }
        __syncthreads();
#pragma unroll 16
        for (int kk = 0; kk < 64; kk++) {
            float a = as_[r][kk];
            a0 = fmaf(xs[mg * 4 + 0][kk], a, a0);
            a1 = fmaf(xs[mg * 4 + 1][kk], a, a1);
            a2 = fmaf(xs[mg * 4 + 2][kk], a, a2);
            a3 = fmaf(xs[mg * 4 + 3][kk], a, a3);
        }
        __syncthreads();
    }
    const __half z = __float2half_rn(0.0f);
#pragma unroll
    for (int q = 0; q < 4; q++) {
        float v = (q == 0 ? a0 : q == 1 ? a1 : q == 2 ? a2 : a3) * scale;
        long long row = bm + mg * 4 + q;
        T[row * 32 + r] = __float2half_rn(v);
        T[row * 32 + 16 + r] = z;
    }
}

// ---------------------------------------------------------------------------
// fp16 2-term mma.sync GEMM: C = Ah * (Bh+Bl)^T + bias + LoRA chunk
// A: (M,K) single fp16; B: (N,K) fp16 hi/lo. 3 tiles/chunk, 3-stage pipeline.
// ---------------------------------------------------------------------------
#define MG_STAGE 24576
#define MG_SMEM  (3 * MG_STAGE)

template<bool SPLIT_OUT>
__global__ void __launch_bounds__(256, 2)
mma_gemm(const __half* __restrict__ Ah,
         const __half* __restrict__ Bh, const __half* __restrict__ Bl,
         const __half* __restrict__ LT,
         const __half* __restrict__ LBh, const __half* __restrict__ LBl,
         float* __restrict__ C, __half* __restrict__ Chi, __half* __restrict__ Clo,
         int K, int N, const float* __restrict__ bias)
{
    extern __shared__ char smem[];
    const uint32_t sb = smem_u32(smem);
    const int tid  = threadIdx.x;
    const int lane = tid & 31;
    const int warp = tid >> 5;
    const int wm   = warp >> 1;
    const int wn   = warp & 1;
    const int bm = blockIdx.y * 128;
    const int bn = blockIdx.x * 128;

    const int KCH = K >> 5;
    const int NC  = KCH + 1;

    float acc[2][8][4];
#pragma unroll
    for (int m = 0; m < 2; m++)
#pragma unroll
        for (int n = 0; n < 8; n++)
#pragma unroll
            for (int j = 0; j < 4; j++) acc[m][n][j] = 0.0f;

    auto load_chunk = [&](int ch, int st) {
        const bool lora = (ch == KCH);
        const int kt = ch << 5;
#pragma unroll
        for (int i = tid; i < 1536; i += 256) {
            int tile = i / 512;          // 0=A, 1=Bh, 2=Bl
            int idx  = i - tile * 512;
            int row  = idx >> 2;
            int c4   = idx & 3;
            const __half* g;
            long long off;
            if (!lora) {
                g = (tile == 0) ? Ah : (tile == 1) ? Bh : Bl;
                int r0 = (tile == 0) ? bm : bn;
                off = (long long)(r0 + row) * K + kt + c4 * 8;
            } else {
                g = (tile == 0) ? LT : (tile == 1) ? LBh : LBl;
                int r0 = (tile == 0) ? bm : bn;
                off = (long long)(r0 + row) * 32 + c4 * 8;
            }
            uint32_t dst = sb + st * MG_STAGE + tile * 8192 + row * 64
                         + ((c4 ^ ((row >> 1) & 3)) << 4);
            cp16(dst, g + off);
        }
        cp_commit();
    };

    load_chunk(0, 0);
    load_chunk(1, 1);

    for (int ch = 0; ch < NC; ch++) {
        const int st = ch % 3;
        if (ch + 2 < NC) {
            load_chunk(ch + 2, (ch + 2) % 3);
            asm volatile("cp.async.wait_group 2;" ::: "memory");
        } else if (ch + 1 < NC) {
            asm volatile("cp.async.wait_group 1;" ::: "memory");
        } else {
            asm volatile("cp.async.wait_group 0;" ::: "memory");
        }
        __syncthreads();

        const uint32_t stb = sb + st * MG_STAGE;
#pragma unroll
        for (int kk = 0; kk < 2; kk++) {
            uint32_t ah[2][4];
#pragma unroll
            for (int mf = 0; mf < 2; mf++) {
                int row = wm * 32 + mf * 16 + (lane & 15);
                int c4  = kk * 2 + (lane >> 4);
                uint32_t sw = (uint32_t)((c4 ^ ((row >> 1) & 3)) << 4);
                ldm_x4(ah[mf][0], ah[mf][1], ah[mf][2], ah[mf][3],
                       stb + row * 64 + sw);
            }
            uint32_t bh[8][2], bl[8][2];
#pragma unroll
            for (int p = 0; p < 4; p++) {
                int row = wn * 64 + p * 16 + (lane & 15);
                int c4  = kk * 2 + (lane >> 4);
                uint32_t sw = (uint32_t)((c4 ^ ((row >> 1) & 3)) << 4);
                uint32_t ad = stb + 8192 + row * 64 + sw;
                uint32_t r0, r1, r2, r3;
                ldm_x4(r0, r1, r2, r3, ad);
                bh[2*p][0] = r0; bh[2*p][1] = r2;
                bh[2*p+1][0] = r1; bh[2*p+1][1] = r3;
                ldm_x4(r0, r1, r2, r3, ad + 8192);
                bl[2*p][0] = r0; bl[2*p][1] = r2;
                bl[2*p+1][0] = r1; bl[2*p+1][1] = r3;
            }
#pragma unroll
            for (int mf = 0; mf < 2; mf++)
#pragma unroll
                for (int n = 0; n < 8; n++) {
                    mma_f16(acc[mf][n], ah[mf], bh[n]);
                    mma_f16(acc[mf][n], ah[mf], bl[n]);
                }
        }
        __syncthreads();
    }

#pragma unroll
    for (int mf = 0; mf < 2; mf++) {
        int r1 = bm + wm * 32 + mf * 16 + (lane >> 2);
#pragma unroll
        for (int n = 0; n < 8; n++) {
            int col = bn + wn * 64 + n * 8 + (lane & 3) * 2;
            float b0 = bias[col], b1 = bias[col + 1];
            float v00 = acc[mf][n][0] + b0, v01 = acc[mf][n][1] + b1;
            float v10 = acc[mf][n][2] + b0, v11 = acc[mf][n][3] + b1;
            if (SPLIT_OUT) {
                __half l0, l1;
                __half2 h = pack_split_h(v00, v01, l0, l1);
                *reinterpret_cast<__half2*>(&Chi[(long long)r1 * N + col]) = h;
                *reinterpret_cast<__half2*>(&Clo[(long long)r1 * N + col]) =
                    __halves2half2(l0, l1);
                h = pack_split_h(v10, v11, l0, l1);
                *reinterpret_cast<__half2*>(&Chi[(long long)(r1 + 8) * N + col]) = h;
                *reinterpret_cast<__half2*>(&Clo[(long long)(r1 + 8) * N + col]) =
                    __halves2half2(l0, l1);
            } else {
                *reinterpret_cast<float2*>(&C[(long long)r1 * N + col]) =
                    make_float2(v00, v01);
                *reinterpret_cast<float2*>(&C[(long long)(r1 + 8) * N + col]) =
                    make_float2(v10, v11);
            }
        }
    }
}

// ---------------------------------------------------------------------------
// Persistent fused attention (256 threads, fp16 3-term, Q double-buffer)
// same smem layout as R16, fp16 types; writes SINGLE fp16 Y.
// ---------------------------------------------------------------------------
#define FA_KH   0
#define FA_KL   32768
#define FA_VH   65536
#define FA_VL   98304
#define FA_Q0   131072
#define FA_PH   147456
#define FA_PL   180224
#define FA_REDM 212992
#define FA_REDS 214016
#define FA_Q1   215040
#define FA_SMEM 231424

__global__ void __launch_bounds__(256)
fa_kernel(const __half* __restrict__ Qh, const __half* __restrict__ Ql,
          const __half* __restrict__ KVh, const __half* __restrict__ KVl,
          __half* __restrict__ Yout)
{
    extern __shared__ char smem[];
    const uint32_t sb = smem_u32(smem);
    const int tid  = threadIdx.x;
    const int lane = tid & 31;
    const int warp = tid >> 5;
    const int bh = blockIdx.x;
    const int b = bh >> 4, h = bh & 15;

    const int rq = lane >> 2, cq = lane & 3;
    const int wm = warp >> 2;
    const int wn = warp & 3;

    float* red_max = reinterpret_cast<float*>(smem + FA_REDM);
    float* red_sum = reinterpret_cast<float*>(smem + FA_REDS);

    const long long qstride = 1024;
    const long long qbase0  = ((long long)(b * 1024)) * 1024 + h * 64;

    auto load_q = [&](int tt, uint32_t qbuf) {
        const long long qbase = qbase0 + (long long)(tt * 64) * qstride;
#pragma unroll
        for (int i = tid; i < 512; i += 256) {
            int row = i >> 3, c = i & 7;
            uint32_t sw = (uint32_t)((c ^ (row & 7)) << 4);
            cp16(sb + qbuf + row * 128 + sw,        Qh + qbase + (long long)row * qstride + c * 8);
            cp16(sb + qbuf + 8192 + row * 128 + sw, Ql + qbase + (long long)row * qstride + c * 8);
        }
        cp_commit();
    };

    {
        const long long kbase = ((long long)(b * 256)) * 2048 + h * 64;
#pragma unroll
        for (int i = tid; i < 2048; i += 256) {
            int row = i >> 3, c = i & 7;
            uint32_t sw = (uint32_t)((c ^ (row & 7)) << 4);
            long long go = (long long)row * 2048 + c * 8;
            cp16(sb + FA_KH + row * 128 + sw, KVh + kbase + go);
            cp16(sb + FA_KL + row * 128 + sw, KVl + kbase + go);
            cp16(sb + FA_VH + row * 128 + sw, KVh + kbase + 1024 + go);
            cp16(sb + FA_VL + row * 128 + sw, KVl + kbase + 1024 + go);
        }
        cp_commit();
        load_q(0, FA_Q0);
        asm volatile("cp.async.wait_group 0;" ::: "memory");
        __syncthreads();
    }

    for (int tt = 0; tt < 16; tt++) {
        const int t0 = tt * 64;
        const bool need_mask = (t0 < Slen);
        const int tmax = t0 + 63;
        const uint32_t qb = (tt & 1) ? FA_Q1 : FA_Q0;

        if (tt > 0) {
            asm volatile("cp.async.wait_group 0;" ::: "memory");
            __syncthreads();
        }

        float acc[2][8][4];
#pragma unroll
        for (int m = 0; m < 2; m++)
#pragma unroll
            for (int n = 0; n < 8; n++)
#pragma unroll
                for (int j = 0; j < 4; j++) acc[m][n][j] = 0.0f;

#pragma unroll
        for (int ks = 0; ks < 4; ks++) {
            uint32_t ah[2][4], al[2][4];
#pragma unroll
            for (int mf = 0; mf < 2; mf++) {
                int row = wm * 32 + mf * 16 + (lane & 15);
                int ch  = ks * 2 + (lane >> 4);
                uint32_t ad = sb + qb + row * 128 + (uint32_t)((ch ^ (row & 7)) << 4);
                ldm_x4(ah[mf][0], ah[mf][1], ah[mf][2], ah[mf][3], ad);
                ldm_x4(al[mf][0], al[mf][1], al[mf][2], al[mf][3], ad + 8192);
            }
            uint32_t bh_[8][2], bl_[8][2];
#pragma unroll
            for (int p = 0; p < 4; p++) {
                if (need_mask && (wn * 64 + p * 16) > tmax) continue;
                int row = wn * 64 + p * 16 + (lane & 15);
                int ch  = ks * 2 + (lane >> 4);
                uint32_t ad = sb + FA_KH + row * 128 + (uint32_t)((ch ^ (row & 7)) << 4);
                uint32_t r0, r1, r2, r3;
                ldm_x4(r0, r1, r2, r3, ad);
                bh_[2*p][0] = r0; bh_[2*p][1] = r2;
                bh_[2*p+1][0] = r1; bh_[2*p+1][1] = r3;
                ldm_x4(r0, r1, r2, r3, ad + 32768);
                bl_[2*p][0] = r0; bl_[2*p][1] = r2;
                bl_[2*p+1][0] = r1; bl_[2*p+1][1] = r3;
            }
#pragma unroll
            for (int mf = 0; mf < 2; mf++)
#pragma unroll
                for (int n = 0; n < 8; n++) {
                    if (need_mask && (wn * 64 + n * 8) > tmax) continue;
                    mma_f16(acc[mf][n], ah[mf], bh_[n]);
                    mma_f16(acc[mf][n], ah[mf], bl_[n]);
                    mma_f16(acc[mf][n], al[mf], bh_[n]);
                }
        }

        if (tt + 1 < 16) load_q(tt + 1, (tt & 1) ? FA_Q0 : FA_Q1);

        // softmax
#pragma unroll
        for (int mf = 0; mf < 2; mf++)
#pragma unroll
            for (int sub = 0; sub < 2; sub++) {
                int rl = wm * 32 + mf * 16 + sub * 8 + rq;
                int trow = t0 + rl;
                float m = -1e30f;
#pragma unroll
                for (int nf = 0; nf < 8; nf++) {
                    int col = wn * 64 + nf * 8 + cq * 2;
                    float v0 = acc[mf][nf][sub*2]     * 0.125f;
                    float v1 = acc[mf][nf][sub*2 + 1] * 0.125f;
                    if (need_mask) {
                        if (col     > trow) v0 = -1e30f;
                        if (col + 1 > trow) v1 = -1e30f;
                    }
                    acc[mf][nf][sub*2]     = v0;
                    acc[mf][nf][sub*2 + 1] = v1;
                    m = fmaxf(m, fmaxf(v0, v1));
                }
                m = fmaxf(m, __shfl_xor_sync(0xffffffffu, m, 1));
                m = fmaxf(m, __shfl_xor_sync(0xffffffffu, m, 2));
                if (cq == 0) red_max[wn * 64 + rl] = m;
            }
        __syncthreads();

#pragma unroll
        for (int mf = 0; mf < 2; mf++)
#pragma unroll
            for (int sub = 0; sub < 2; sub++) {
                int rl = wm * 32 + mf * 16 + sub * 8 + rq;
                float M = fmaxf(fmaxf(red_max[rl], red_max[64 + rl]),
                                fmaxf(red_max[128 + rl], red_max[192 + rl]));
                float s = 0.0f;
#pragma unroll
                for (int nf = 0; nf < 8; nf++) {
                    float e0 = __expf(acc[mf][nf][sub*2]     - M);
                    float e1 = __expf(acc[mf][nf][sub*2 + 1] - M);
                    acc[mf][nf][sub*2]     = e0;
                    acc[mf][nf][sub*2 + 1] = e1;
                    s += e0 + e1;
                }
                s += __shfl_xor_sync(0xffffffffu, s, 1);
                s += __shfl_xor_sync(0xffffffffu, s, 2);
                if (cq == 0) red_sum[wn * 64 + rl] = s;
            }
        __syncthreads();

        // store P (unnormalized) split fp16
#pragma unroll
        for (int mf = 0; mf < 2; mf++)
#pragma unroll
            for (int sub = 0; sub < 2; sub++) {
                int rl = wm * 32 + mf * 16 + sub * 8 + rq;
#pragma unroll
                for (int nf = 0; nf < 8; nf++) {
                    int col = wn * 64 + nf * 8 + cq * 2;
                    __half l0, l1;
                    __half2 hh = pack_split_h(acc[mf][nf][sub*2],
                                              acc[mf][nf][sub*2 + 1], l0, l1);
                    int chnk = col >> 3;
                    uint32_t off = (uint32_t)(rl * 512 + ((chnk ^ (rl & 7)) << 4) + (col & 7) * 2);
                    *reinterpret_cast<__half2*>(smem + FA_PH + off) = hh;
                    *reinterpret_cast<__half2*>(smem + FA_PL + off) = __halves2half2(l0, l1);
                }
            }
        __syncthreads();

        // Y = P V
        const int nks = need_mask ? ((tmax >> 4) + 1) : 16;
        float acc2[2][2][4];
#pragma unroll
        for (int m = 0; m < 2; m++)
#pragma unroll
            for (int n = 0; n < 2; n++)
#pragma unroll
                for (int j = 0; j < 4; j++) acc2[m][n][j] = 0.0f;

        for (int ks = 0; ks < nks; ks++) {
            uint32_t ph[2][4], pl[2][4];
#pragma unroll
            for (int mf = 0; mf < 2; mf++) {
                int row = wm * 32 + mf * 16 + (lane & 15);
                int ch  = ks * 2 + (lane >> 4);
                uint32_t ad = sb + FA_PH + row * 512 + (uint32_t)((ch ^ (row & 7)) << 4);
                ldm_x4(ph[mf][0], ph[mf][1], ph[mf][2], ph[mf][3], ad);
                ldm_x4(pl[mf][0], pl[mf][1], pl[mf][2], pl[mf][3], ad + 32768);
            }
            uint32_t vh_[2][2], vl_[2][2];
            {
                int g = lane >> 3;
                int srow = ks * 16 + (g & 1) * 8 + (lane & 7);
                int dch  = wn * 2 + (g >> 1);
                uint32_t ad = sb + FA_VH + srow * 128 + (uint32_t)((dch ^ (srow & 7)) << 4);
                uint32_t r0, r1, r2, r3;
                ldm_x4t(r0, r1, r2, r3, ad);
                vh_[0][0] = r0; vh_[0][1] = r1; vh_[1][0] = r2; vh_[1][1] = r3;
                ldm_x4t(r0, r1, r2, r3, ad + 32768);
                vl_[0][0] = r0; vl_[0][1] = r1; vl_[1][0] = r2; vl_[1][1] = r3;
            }
#pragma unroll
            for (int mf = 0; mf < 2; mf++)
#pragma unroll
                for (int nf = 0; nf < 2; nf++) {
                    mma_f16(acc2[mf][nf], ph[mf], vh_[nf]);
                    mma_f16(acc2[mf][nf], ph[mf], vl_[nf]);
                    mma_f16(acc2[mf][nf], pl[mf], vh_[nf]);
                }
        }

        // epilogue: normalize, single fp16 Y
#pragma unroll
        for (int mf = 0; mf < 2; mf++)
#pragma unroll
            for (int sub = 0; sub < 2; sub++) {
                int rl = wm * 32 + mf * 16 + sub * 8 + rq;
                float inv = 1.0f / (red_sum[rl] + red_sum[64 + rl] +
                                    red_sum[128 + rl] + red_sum[192 + rl]);
                long long yo = ((long long)(b * 1024 + t0 + rl)) * 1024 + h * 64;
#pragma unroll
                for (int nf = 0; nf < 2; nf++) {
                    int col = wn * 16 + nf * 8 + cq * 2;
                    float v0 = acc2[mf][nf][sub*2]     * inv;
                    float v1 = acc2[mf][nf][sub*2 + 1] * inv;
                    *reinterpret_cast<__half2*>(&Yout[yo + col]) = __floats2half2_rn(v0, v1);
                }
            }
        __syncthreads();
    }
}

// ---------------------------------------------------------------------------
// Launch
// ---------------------------------------------------------------------------
extern "C" void kernel_launch(void* const* d_in, const int* in_sizes, int n_in,
                              void* d_out, int out_size)
{
    const float* x  = (const float*)d_in[0];
    const float* ft = (const float*)d_in[1];
    const float* Wq = (const float*)d_in[2];
    const float* bq = (const float*)d_in[3];
    const float* Aq = (const float*)d_in[4];
    const float* Bq = (const float*)d_in[5];
    const float* Wf = (const float*)d_in[6];
    const float* bfv= (const float*)d_in[7];
    const float* Af = (const float*)d_in[8];
    const float* Bf = (const float*)d_in[9];
    const float* Wp = (const float*)d_in[10];
    const float* bp = (const float*)d_in[11];
    const float* Ap = (const float*)d_in[12];
    const float* Bp = (const float*)d_in[13];
    float* out = (float*)d_out;

    __half *xh, *fh, *yh;
    __half *wqh, *wql, *wfh, *wfl, *wph, *wpl;
    __half *qh, *ql, *kvh, *kvl;
    __half *tq, *tf, *tp;
    __half *bqh, *bql, *bfh, *bfl, *bph, *bpl;
    cudaGetSymbolAddress((void**)&xh, g_xh);   cudaGetSymbolAddress((void**)&fh, g_fh);
    cudaGetSymbolAddress((void**)&yh, g_yh);
    cudaGetSymbolAddress((void**)&wqh, g_wqh); cudaGetSymbolAddress((void**)&wql, g_wql);
    cudaGetSymbolAddress((void**)&wfh, g_wfh); cudaGetSymbolAddress((void**)&wfl, g_wfl);
    cudaGetSymbolAddress((void**)&wph, g_wph); cudaGetSymbolAddress((void**)&wpl, g_wpl);
    cudaGetSymbolAddress((void**)&qh, g_qh);   cudaGetSymbolAddress((void**)&ql, g_ql);
    cudaGetSymbolAddress((void**)&kvh, g_kvh); cudaGetSymbolAddress((void**)&kvl, g_kvl);
    cudaGetSymbolAddress((void**)&tq, g_tq);   cudaGetSymbolAddress((void**)&tf, g_tf);
    cudaGetSymbolAddress((void**)&tp, g_tp);
    cudaGetSymbolAddress((void**)&bqh, g_bqh); cudaGetSymbolAddress((void**)&bql, g_bql);
    cudaGetSymbolAddress((void**)&bfh, g_bfh); cudaGetSymbolAddress((void**)&bfl, g_bfl);
    cudaGetSymbolAddress((void**)&bph, g_bph); cudaGetSymbolAddress((void**)&bpl, g_bpl);

    cudaFuncSetAttribute(mma_gemm<false>, cudaFuncAttributeMaxDynamicSharedMemorySize, MG_SMEM);
    cudaFuncSetAttribute(mma_gemm<true>,  cudaFuncAttributeMaxDynamicSharedMemorySize, MG_SMEM);
    cudaFuncSetAttribute(fa_kernel, cudaFuncAttributeMaxDynamicSharedMemorySize, FA_SMEM);

    const float SC = 1.0f / 16.0f;

    split_act<<<(AF4 + 255)/256, 256>>>((const float4*)x, (const float4*)ft,
                                        (__half2*)xh, (__half2*)fh);
    split_w<<<(WP4 + 255)/256, 256>>>((const float4*)Wq, (const float4*)Wf, (const float4*)Wp,
                                      (__half2*)wqh, (__half2*)wql,
                                      (__half2*)wfh, (__half2*)wfl,
                                      (__half2*)wph, (__half2*)wpl);

    lora_t_merged<<<160, 256>>>(x, Aq, ft, Af, tq, tf, SC);
    splitpad_multi<<<128, 256>>>(Bq, Bf, Bp, bqh, bql, bfh, bfl, bph, bpl);

    // Q projection -> split fp16
    mma_gemm<true><<<dim3(8, 64), 256, MG_SMEM>>>(xh, wqh, wql,
        tq, bqh, bql, nullptr, qh, ql, 1024, 1024, bq);

    // KV projection -> split fp16
    mma_gemm<true><<<dim3(16, 16), 256, MG_SMEM>>>(fh, wfh, wfl,
        tf, bfh, bfl, nullptr, kvh, kvl, 1024, 2048, bfv);

    // persistent fused attention -> single fp16 Y
    fa_kernel<<<128, 256, FA_SMEM>>>(qh, ql, kvh, kvl, yh);

    // LoRA for P from fp16 Y
    lora_t_half<<<128, 256>>>(yh, Ap, tp, SC);

    // out = y @ Wp^T + bp + lora  (fp32 out)
    mma_gemm<false><<<dim3(8, 64), 256, MG_SMEM>>>(yh, wph, wpl,
        tp, bph, bpl, out, nullptr, nullptr, 1024, 1024, bp);
}